// round 9
// baseline (speedup 1.0000x reference)
#include <cuda_runtime.h>
#include <cuda_bf16.h>
#include <cstdint>

#define BATCH   64
#define TSTEPS  128
#define TB      8192
#define DIN     768
#define H1      512
#define G1N     2048
#define H2      256
#define G2N     1024

// ---------------- static device scratch (no allocations) ----------------
__device__ float g_G1[(size_t)TB * G1N];   // 64 MB
__device__ float g_G2[(size_t)TB * G2N];   // 32 MB
__device__ float g_hs1[(size_t)TB * H1];   // 16 MB
__device__ float g_hT[2][H1 * BATCH];      // h1 transposed [j][b], double-buffered
__device__ float g_c1[BATCH * H1];         // LSTM1 cell state [b][j]
__device__ float g_hT2[H2];                // final LSTM2 hidden

__device__ __forceinline__ float sigf(float x) { return 1.0f / (1.0f + __expf(-x)); }

__global__ void zero_state() {
    int id = blockIdx.x * blockDim.x + threadIdx.x;   // 32768 threads
    g_c1[id] = 0.0f;
    g_hT[0][id] = 0.0f;
}

// ---------------- GEMM: C[M,N] = A[M,K] @ B[N,K]^T + bias1 + bias2 ----------------
template <int MODE>
__global__ void __launch_bounds__(256) gemm64(const float* __restrict__ A,
                                              const float* __restrict__ B,
                                              const float* __restrict__ bias1,
                                              const float* __restrict__ bias2) {
    constexpr int N = (MODE == 0) ? G1N : G2N;
    constexpr int K = (MODE == 0) ? DIN : H1;
    float* __restrict__ C = (MODE == 0) ? g_G1 : g_G2;
    const float* __restrict__ Ap = (MODE == 0) ? A : g_hs1;

    __shared__ float As[16][64];
    __shared__ float Bs[16][64];

    int tid = threadIdx.x;
    int m0 = blockIdx.y * 64, n0 = blockIdx.x * 64;
    int tx = tid & 15, ty = tid >> 4;

    int la_m = tid & 63, la_k = (tid >> 6) * 4;
    int lb_n = tid >> 2, lb_k = (tid & 3) * 4;

    int r = m0 + la_m;
    size_t arow;
    if (MODE == 0) {
        int b = r & 63, t = r >> 6;
        arow = ((size_t)b * TSTEPS + t) * DIN;
    } else {
        arow = (size_t)r * K;
    }

    float acc[4][4];
#pragma unroll
    for (int i = 0; i < 4; i++)
#pragma unroll
        for (int j = 0; j < 4; j++) acc[i][j] = 0.0f;

    for (int kt = 0; kt < K; kt += 16) {
        float4 av = *(const float4*)(Ap + arow + kt + la_k);
        As[la_k + 0][la_m] = av.x;
        As[la_k + 1][la_m] = av.y;
        As[la_k + 2][la_m] = av.z;
        As[la_k + 3][la_m] = av.w;
        float4 bv = *(const float4*)(B + (size_t)(n0 + lb_n) * K + kt + lb_k);
        Bs[lb_k + 0][lb_n] = bv.x;
        Bs[lb_k + 1][lb_n] = bv.y;
        Bs[lb_k + 2][lb_n] = bv.z;
        Bs[lb_k + 3][lb_n] = bv.w;
        __syncthreads();
#pragma unroll
        for (int k = 0; k < 16; k++) {
            float4 a  = ((const float4*)As[k])[ty];
            float4 b4 = ((const float4*)Bs[k])[tx];
            acc[0][0] = fmaf(a.x, b4.x, acc[0][0]);
            acc[0][1] = fmaf(a.x, b4.y, acc[0][1]);
            acc[0][2] = fmaf(a.x, b4.z, acc[0][2]);
            acc[0][3] = fmaf(a.x, b4.w, acc[0][3]);
            acc[1][0] = fmaf(a.y, b4.x, acc[1][0]);
            acc[1][1] = fmaf(a.y, b4.y, acc[1][1]);
            acc[1][2] = fmaf(a.y, b4.z, acc[1][2]);
            acc[1][3] = fmaf(a.y, b4.w, acc[1][3]);
            acc[2][0] = fmaf(a.z, b4.x, acc[2][0]);
            acc[2][1] = fmaf(a.z, b4.y, acc[2][1]);
            acc[2][2] = fmaf(a.z, b4.z, acc[2][2]);
            acc[2][3] = fmaf(a.z, b4.w, acc[2][3]);
            acc[3][0] = fmaf(a.w, b4.x, acc[3][0]);
            acc[3][1] = fmaf(a.w, b4.y, acc[3][1]);
            acc[3][2] = fmaf(a.w, b4.z, acc[3][2]);
            acc[3][3] = fmaf(a.w, b4.w, acc[3][3]);
        }
        __syncthreads();
    }

    int coln = n0 + tx * 4;
    float bb0 = bias1[coln + 0] + bias2[coln + 0];
    float bb1 = bias1[coln + 1] + bias2[coln + 1];
    float bb2 = bias1[coln + 2] + bias2[coln + 2];
    float bb3 = bias1[coln + 3] + bias2[coln + 3];
#pragma unroll
    for (int i = 0; i < 4; i++) {
        int row = m0 + ty * 4 + i;
        float4 o;
        o.x = acc[i][0] + bb0;
        o.y = acc[i][1] + bb1;
        o.z = acc[i][2] + bb2;
        o.w = acc[i][3] + bb3;
        *(float4*)(C + (size_t)row * N + coln) = o;
    }
}

// ---------------- LSTM1 fused step (unchanged from passing R7) ----------------
__global__ void __launch_bounds__(512) lstm1_step(const float* __restrict__ Whh1, int t) {
    __shared__ float Hs[2][64 * 64];
    __shared__ float Ws[2][64 * 16];
    __shared__ float sg[16 * 64];

    int tid = threadIdx.x;
    int half = tid >> 8;
    int lt = tid & 255;
    int c  = lt & 15;
    int bg = lt >> 4;
    int j0 = blockIdx.x * 4;
    int gg_ = c >> 2, u = c & 3;
    int rp = t & 1;
    const float* hsrc = g_hT[rp];

    float a0 = 0.f, a1 = 0.f, a2 = 0.f, a3 = 0.f;
#pragma unroll
    for (int kk = 0; kk < 4; kk++) {
        int kt = half * 256 + kk * 64;
        const float4* src = (const float4*)(hsrc + kt * 64);
        float4* dst = (float4*)Hs[half];
#pragma unroll
        for (int i = 0; i < 4; i++) dst[lt + i * 256] = src[lt + i * 256];
        {
            int wc = lt & 15, wk4 = lt >> 4;
            int wg = wc >> 2, wu = wc & 3;
            float4 wv = *(const float4*)(Whh1 + (size_t)(wg * H1 + j0 + wu) * H1 + kt + wk4 * 4);
            float* W = Ws[half];
            W[(wk4 * 4 + 0) * 16 + wc] = wv.x;
            W[(wk4 * 4 + 1) * 16 + wc] = wv.y;
            W[(wk4 * 4 + 2) * 16 + wc] = wv.z;
            W[(wk4 * 4 + 3) * 16 + wc] = wv.w;
        }
        __syncthreads();
        const float* HH = Hs[half];
        const float* WW = Ws[half];
#pragma unroll 16
        for (int k = 0; k < 64; k++) {
            float4 h4 = ((const float4*)(HH + k * 64))[bg];
            float w = WW[k * 16 + c];
            a0 = fmaf(h4.x, w, a0);
            a1 = fmaf(h4.y, w, a1);
            a2 = fmaf(h4.z, w, a2);
            a3 = fmaf(h4.w, w, a3);
        }
        __syncthreads();
    }

    int b0 = bg * 4;
    int gcol = gg_ * H1 + j0 + u;
    if (half == 0) {
        size_t gbase = ((size_t)(t * BATCH + b0)) * G1N + gcol;
        sg[c * 64 + b0 + 0] = a0 + g_G1[gbase];
        sg[c * 64 + b0 + 1] = a1 + g_G1[gbase + G1N];
        sg[c * 64 + b0 + 2] = a2 + g_G1[gbase + 2 * (size_t)G1N];
        sg[c * 64 + b0 + 3] = a3 + g_G1[gbase + 3 * (size_t)G1N];
    }
    __syncthreads();
    if (half == 1) {
        sg[c * 64 + b0 + 0] += a0;
        sg[c * 64 + b0 + 1] += a1;
        sg[c * 64 + b0 + 2] += a2;
        sg[c * 64 + b0 + 3] += a3;
    }
    __syncthreads();

    if (tid < 256) {
        int u2 = tid >> 6, b = tid & 63;
        float gi = sigf(sg[(0 * 4 + u2) * 64 + b]);
        float gf = sigf(sg[(1 * 4 + u2) * 64 + b]);
        float gc = tanhf(sg[(2 * 4 + u2) * 64 + b]);
        float go = sigf(sg[(3 * 4 + u2) * 64 + b]);
        int jj = j0 + u2;
        int ci = b * H1 + jj;
        float cc = fmaf(gf, g_c1[ci], gi * gc);
        g_c1[ci] = cc;
        float h = go * tanhf(cc);
        g_hT[rp ^ 1][jj * BATCH + b] = h;
        g_hs1[((size_t)(t * BATCH + b)) * H1 + jj] = h;
    }
}

// ---------------- LSTM2: warp-autonomous steps, no per-step __syncthreads ----------------
// lane = g*8 + kq*2 + (j&1), warp = j>>1. Barriers count 128 (8 CTAs x 16 warps).
__device__ __forceinline__ void mbar_wait_cluster(uint32_t mbar, uint32_t parity) {
    asm volatile(
        "{\n\t"
        ".reg .pred P;\n\t"
        "WAIT_%=:\n\t"
        "mbarrier.try_wait.parity.acquire.cluster.shared::cta.b64 P, [%0], %1, 0x989680;\n\t"
        "@P bra.uni DONE_%=;\n\t"
        "bra.uni WAIT_%=;\n\t"
        "DONE_%=:\n\t"
        "}" :: "r"(mbar), "r"(parity) : "memory");
}

__global__ void __cluster_dims__(8, 1, 1) __launch_bounds__(512, 1)
lstm2_kernel(const float* __restrict__ Whh2) {
    __shared__ __align__(16) float sh_h[2][H2];
    __shared__ __align__(8) unsigned long long bar2[2];   // [input-buffer parity]

    int tid = threadIdx.x;
    int w = tid >> 5, l = tid & 31;
    uint32_t rank;
    asm("mov.u32 %0, %%cluster_ctarank;" : "=r"(rank));

    int j  = 2 * w + (l & 1);     // unit within this CTA's 32-slice
    int kq = (l >> 1) & 3;        // k quarter
    int g  = l >> 3;              // gate 0=i 1=f 2=g 3=o
    int gr = g * H2 + (int)rank * 32 + j;
    bool isU = ((l & 6) == 0);    // kq==0 lanes

    // weights: 64 floats of row gr, quarter kq, packed as f32x2
    unsigned long long w2[32];
    {
        const ulonglong2* wp = (const ulonglong2*)(Whh2 + (size_t)gr * H2 + kq * 64);
#pragma unroll
        for (int i = 0; i < 16; i++) {
            ulonglong2 v = wp[i];
            w2[2 * i] = v.x; w2[2 * i + 1] = v.y;
        }
    }

    if (tid < H2) sh_h[0][tid] = 0.0f;
    uint32_t barb = (uint32_t)__cvta_generic_to_shared(&bar2[0]);
    if (tid < 2) {
        uint32_t a = barb + (uint32_t)tid * 8u;
        asm volatile("mbarrier.init.shared.b64 [%0], %1;" :: "r"(a), "r"(128) : "memory");
    }
    __syncthreads();
    asm volatile("barrier.cluster.arrive.aligned;" ::: "memory");
    asm volatile("barrier.cluster.wait.aligned;" ::: "memory");

    // precompute remote addresses (used by lane 0 of each warp)
    uint32_t hb = (uint32_t)__cvta_generic_to_shared(&sh_h[0][0]);
    uint32_t ph0[8], ph1[8], pb0[8], pb1[8];
    {
        uint32_t l0 = hb + (uint32_t)((int)rank * 32 + 2 * w) * 4u;  // 8B-aligned (2w even)
        uint32_t l1 = l0 + H2 * 4u;
#pragma unroll
        for (int d = 0; d < 8; d++) {
            asm("mapa.shared::cluster.u32 %0, %1, %2;" : "=r"(ph0[d]) : "r"(l0), "r"(d));
            asm("mapa.shared::cluster.u32 %0, %1, %2;" : "=r"(ph1[d]) : "r"(l1), "r"(d));
            asm("mapa.shared::cluster.u32 %0, %1, %2;" : "=r"(pb0[d]) : "r"(barb), "r"(d));
            asm("mapa.shared::cluster.u32 %0, %1, %2;" : "=r"(pb1[d]) : "r"(barb + 8u), "r"(d));
        }
    }

    float c = 0.0f;
    float u_next = isU ? __ldg(&g_G2[gr]) : 0.0f;
    uint32_t ph[2] = {0u, 0u};

    for (int r = 0; r < TB; r++) {
        int buf = r & 1;
        if (r > 0) {
            if (l == 0) mbar_wait_cluster(barb + (uint32_t)buf * 8u, ph[buf]);
            __syncwarp();
            ph[buf] ^= 1u;
        }

        float u = u_next;
        if (isU && r + 1 < TB) u_next = __ldg(&g_G2[(size_t)(r + 1) * G2N + gr]);

        const ulonglong2* hp = (const ulonglong2*)(&sh_h[buf][kq * 64]);
        unsigned long long acc01 = 0ull, acc23 = 0ull;
#pragma unroll
        for (int i = 0; i < 16; i++) {
            ulonglong2 hv = hp[i];
            asm("fma.rn.f32x2 %0, %1, %2, %3;" : "=l"(acc01) : "l"(w2[2 * i]), "l"(hv.x), "l"(acc01));
            asm("fma.rn.f32x2 %0, %1, %2, %3;" : "=l"(acc23) : "l"(w2[2 * i + 1]), "l"(hv.y), "l"(acc23));
        }
        float acc = (__uint_as_float((unsigned)acc01) + __uint_as_float((unsigned)(acc01 >> 32)))
                  + (__uint_as_float((unsigned)acc23) + __uint_as_float((unsigned)(acc23 >> 32)));
        // reduce over kq (lane bits 1-2)
        acc += __shfl_xor_sync(0xffffffffu, acc, 2);
        acc += __shfl_xor_sync(0xffffffffu, acc, 4);

        float act = 0.0f;
        if (isU) {
            float pre = acc + u;
            act = (g == 2) ? tanhf(pre) : sigf(pre);
        }
        // gather the 4 gates for this lane's unit j (from kq==0 lanes)
        int jb = l & 1;
        float gi = __shfl_sync(0xffffffffu, act, jb);
        float gf = __shfl_sync(0xffffffffu, act, 8 | jb);
        float gg = __shfl_sync(0xffffffffu, act, 16 | jb);
        float go = __shfl_sync(0xffffffffu, act, 24 | jb);

        c = fmaf(gf, c, gi * gg);            // redundant across the 16 lanes sharing j
        float h = go * tanhf(c);

        float h0 = __shfl_sync(0xffffffffu, h, 0);   // unit 2w
        float h1 = __shfl_sync(0xffffffffu, h, 1);   // unit 2w+1

        int nb = buf ^ 1;
        if (l == 0) {
            unsigned long long hv = ((unsigned long long)__float_as_uint(h1) << 32)
                                  | (unsigned long long)__float_as_uint(h0);
            if (nb == 0) {
#pragma unroll
                for (int d = 0; d < 8; d++)
                    asm volatile("st.shared::cluster.u64 [%0], %1;" :: "r"(ph0[d]), "l"(hv) : "memory");
#pragma unroll
                for (int d = 0; d < 8; d++)
                    asm volatile("mbarrier.arrive.release.cluster.shared::cluster.b64 _, [%0];"
                                 :: "r"(pb0[d]) : "memory");
            } else {
#pragma unroll
                for (int d = 0; d < 8; d++)
                    asm volatile("st.shared::cluster.u64 [%0], %1;" :: "r"(ph1[d]), "l"(hv) : "memory");
#pragma unroll
                for (int d = 0; d < 8; d++)
                    asm volatile("mbarrier.arrive.release.cluster.shared::cluster.b64 _, [%0];"
                                 :: "r"(pb1[d]) : "memory");
            }
        }
    }

    // final h (after step TB-1) lives in buf 0; wait for the last arrival batch
    if (l == 0) mbar_wait_cluster(barb, ph[0]);
    __syncwarp();
    __syncthreads();
    if (rank == 0 && tid < H2) g_hT2[tid] = sh_h[0][tid];

    asm volatile("barrier.cluster.arrive.aligned;" ::: "memory");
    asm volatile("barrier.cluster.wait.aligned;" ::: "memory");
}

// ---------------- tail MLP ----------------
__global__ void mlp_kernel(const float* __restrict__ W1, const float* __restrict__ b1,
                           const float* __restrict__ W2, const float* __restrict__ b2,
                           float* __restrict__ out) {
    __shared__ float emb[H2];
    __shared__ float o1[128];
    int tid = threadIdx.x;  // 128
    {
        float h0 = g_hT2[tid];
        float h1 = g_hT2[tid + 128];
        emb[tid]       = h0 + h0 * h0;
        emb[tid + 128] = h1 + h1 * h1;
    }
    __syncthreads();
    float s = b1[tid];
    const float* wrow = W1 + (size_t)tid * H2;
#pragma unroll 8
    for (int k = 0; k < H2; k++) s = fmaf(emb[k], wrow[k], s);
    o1[tid] = s;
    __syncthreads();
    if (tid < 10) {
        float s2 = b2[tid];
        const float* w2r = W2 + (size_t)tid * 128;
#pragma unroll 8
        for (int k = 0; k < 128; k++) s2 = fmaf(o1[k], w2r[k], s2);
        out[tid] = s2;
    }
}

extern "C" void kernel_launch(void* const* d_in, const int* in_sizes, int n_in,
                              void* d_out, int out_size) {
    const float* x     = (const float*)d_in[0];
    const float* W_ih1 = (const float*)d_in[1];
    const float* W_hh1 = (const float*)d_in[2];
    const float* b_ih1 = (const float*)d_in[3];
    const float* b_hh1 = (const float*)d_in[4];
    const float* W_ih2 = (const float*)d_in[5];
    const float* W_hh2 = (const float*)d_in[6];
    const float* b_ih2 = (const float*)d_in[7];
    const float* b_hh2 = (const float*)d_in[8];
    const float* W1    = (const float*)d_in[9];
    const float* b1    = (const float*)d_in[10];
    const float* W2    = (const float*)d_in[11];
    const float* b2    = (const float*)d_in[12];
    float* out = (float*)d_out;

    zero_state<<<128, 256>>>();

    gemm64<0><<<dim3(G1N / 64, TB / 64), 256>>>(x, W_ih1, b_ih1, b_hh1);

    for (int t = 0; t < TSTEPS; t++) {
        lstm1_step<<<128, 512>>>(W_hh1, t);
    }

    gemm64<1><<<dim3(G2N / 64, TB / 64), 256>>>(x, W_ih2, b_ih2, b_hh2);

    lstm2_kernel<<<8, 512>>>(W_hh2);

    mlp_kernel<<<1, 128>>>(W1, b1, W2, b2, out);
}

// round 13
// speedup vs baseline: 1.2046x; 1.2046x over previous
#include <cuda_runtime.h>
#include <cuda_bf16.h>
#include <cstdint>

#define BATCH   64
#define TSTEPS  128
#define TB      8192
#define DIN     768
#define H1      512
#define G1N     2048
#define H2      256
#define G2N     1024

// ---------------- static device scratch (no allocations) ----------------
__device__ float g_G1[(size_t)TB * G1N];   // 64 MB
__device__ float g_G2[(size_t)TB * G2N];   // 32 MB
__device__ float g_hs1[(size_t)TB * H1];   // 16 MB
__device__ float g_hT[2][H1 * BATCH];      // h1 transposed [j][b], double-buffered
__device__ float g_hT2[H2];                // final LSTM2 hidden
__device__ unsigned g_bar;                 // lstm1 global barrier counter

__device__ __forceinline__ float sigf(float x) { return 1.0f / (1.0f + __expf(-x)); }
__device__ __forceinline__ float tanh_fast(float x) {
    float xc = fminf(fmaxf(x, -15.0f), 15.0f);
    float e = __expf(2.0f * xc);
    return __fdividef(e - 1.0f, e + 1.0f);
}

__global__ void zero_state() {
    int id = blockIdx.x * blockDim.x + threadIdx.x;   // 32768 threads
    g_hT[0][id] = 0.0f;
    if (id == 0) g_bar = 0u;
}

__global__ void noop_kernel() {}

// ---------------- GEMM: C[M,N] = A[M,K] @ B[N,K]^T + bias1 + bias2 ----------------
template <int MODE>
__global__ void __launch_bounds__(256) gemm64(const float* __restrict__ A,
                                              const float* __restrict__ B,
                                              const float* __restrict__ bias1,
                                              const float* __restrict__ bias2) {
    constexpr int N = (MODE == 0) ? G1N : G2N;
    constexpr int K = (MODE == 0) ? DIN : H1;
    float* __restrict__ C = (MODE == 0) ? g_G1 : g_G2;
    const float* __restrict__ Ap = (MODE == 0) ? A : g_hs1;

    __shared__ float As[16][64];
    __shared__ float Bs[16][64];

    int tid = threadIdx.x;
    int m0 = blockIdx.y * 64, n0 = blockIdx.x * 64;
    int tx = tid & 15, ty = tid >> 4;

    int la_m = tid & 63, la_k = (tid >> 6) * 4;
    int lb_n = tid >> 2, lb_k = (tid & 3) * 4;

    int r = m0 + la_m;
    size_t arow;
    if (MODE == 0) {
        int b = r & 63, t = r >> 6;
        arow = ((size_t)b * TSTEPS + t) * DIN;
    } else {
        arow = (size_t)r * K;
    }

    float acc[4][4];
#pragma unroll
    for (int i = 0; i < 4; i++)
#pragma unroll
        for (int j = 0; j < 4; j++) acc[i][j] = 0.0f;

    for (int kt = 0; kt < K; kt += 16) {
        float4 av = *(const float4*)(Ap + arow + kt + la_k);
        As[la_k + 0][la_m] = av.x;
        As[la_k + 1][la_m] = av.y;
        As[la_k + 2][la_m] = av.z;
        As[la_k + 3][la_m] = av.w;
        float4 bv = *(const float4*)(B + (size_t)(n0 + lb_n) * K + kt + lb_k);
        Bs[lb_k + 0][lb_n] = bv.x;
        Bs[lb_k + 1][lb_n] = bv.y;
        Bs[lb_k + 2][lb_n] = bv.z;
        Bs[lb_k + 3][lb_n] = bv.w;
        __syncthreads();
#pragma unroll
        for (int k = 0; k < 16; k++) {
            float4 a  = ((const float4*)As[k])[ty];
            float4 b4 = ((const float4*)Bs[k])[tx];
            acc[0][0] = fmaf(a.x, b4.x, acc[0][0]);
            acc[0][1] = fmaf(a.x, b4.y, acc[0][1]);
            acc[0][2] = fmaf(a.x, b4.z, acc[0][2]);
            acc[0][3] = fmaf(a.x, b4.w, acc[0][3]);
            acc[1][0] = fmaf(a.y, b4.x, acc[1][0]);
            acc[1][1] = fmaf(a.y, b4.y, acc[1][1]);
            acc[1][2] = fmaf(a.y, b4.z, acc[1][2]);
            acc[1][3] = fmaf(a.y, b4.w, acc[1][3]);
            acc[2][0] = fmaf(a.z, b4.x, acc[2][0]);
            acc[2][1] = fmaf(a.z, b4.y, acc[2][1]);
            acc[2][2] = fmaf(a.z, b4.z, acc[2][2]);
            acc[2][3] = fmaf(a.z, b4.w, acc[2][3]);
            acc[3][0] = fmaf(a.w, b4.x, acc[3][0]);
            acc[3][1] = fmaf(a.w, b4.y, acc[3][1]);
            acc[3][2] = fmaf(a.w, b4.z, acc[3][2]);
            acc[3][3] = fmaf(a.w, b4.w, acc[3][3]);
        }
        __syncthreads();
    }

    int coln = n0 + tx * 4;
    float bb0 = bias1[coln + 0] + bias2[coln + 0];
    float bb1 = bias1[coln + 1] + bias2[coln + 1];
    float bb2 = bias1[coln + 2] + bias2[coln + 2];
    float bb3 = bias1[coln + 3] + bias2[coln + 3];
#pragma unroll
    for (int i = 0; i < 4; i++) {
        int row = m0 + ty * 4 + i;
        float4 o;
        o.x = acc[i][0] + bb0;
        o.y = acc[i][1] + bb1;
        o.z = acc[i][2] + bb2;
        o.w = acc[i][3] + bb3;
        *(float4*)(C + (size_t)row * N + coln) = o;
    }
}

// ---------------- LSTM1: single persistent kernel, 128 resident blocks ----------------
// Block handles 4 hidden units for all 64 batches; W slice SMEM-resident for all steps.
// Global sense barrier (monotonic counter); double-buffered g_hT => one barrier/step.
__global__ void __launch_bounds__(512) lstm1_persist(const float* __restrict__ Whh1) {
    extern __shared__ float dsm[];
    float* Hs  = dsm;                          // [2][256*64]  128 KB (both halves)
    float* Wsr = dsm + 2 * 16384;              // [2][256*16]  32 KB
    float* sg  = dsm + 2 * 16384 + 2 * 4096;   // [16*64]      4 KB

    int tid = threadIdx.x;
    int half = tid >> 8;       // k-range half: [half*256, half*256+256)
    int lt = tid & 255;
    int c  = lt & 15;          // local gate column 0..15
    int bg = lt >> 4;          // batch group 0..15
    int j0 = blockIdx.x * 4;
    int gg_ = c >> 2, u = c & 3;
    int gcol = gg_ * H1 + j0 + u;

    // Preload resident weights for this half (256 k x 16 cols)
    {
        int wc = lt & 15, wk4 = lt >> 4;
        int wg = wc >> 2, wu = wc & 3;
        float* W = Wsr + half * 4096;
#pragma unroll
        for (int kk = 0; kk < 4; kk++) {
            int ktl = kk * 64 + wk4 * 4;   // local k 0..255 (step 4)
            float4 wv = *(const float4*)(Whh1 + (size_t)(wg * H1 + j0 + wu) * H1 + half * 256 + ktl);
            W[(ktl + 0) * 16 + wc] = wv.x;
            W[(ktl + 1) * 16 + wc] = wv.y;
            W[(ktl + 2) * 16 + wc] = wv.z;
            W[(ktl + 3) * 16 + wc] = wv.w;
        }
    }

    int u2 = tid >> 6, bb = tid & 63;   // pointwise ids (valid for tid<256)
    float creg = 0.0f;                  // cell state for (j0+u2, bb)

    for (int t = 0; t < TSTEPS; t++) {
        int rp = t & 1;
        // stage this half's h: 16384 floats = 4096 float4s (FIX: was 1024)
        {
            const float4* s4 = (const float4*)(g_hT[rp] + half * 256 * 64);
            float4* d4 = (float4*)(Hs + half * 16384);
#pragma unroll
            for (int i = 0; i < 16; i++) d4[lt + i * 256] = s4[lt + i * 256];
        }
        __syncthreads();

        float a0 = 0.f, a1 = 0.f, a2 = 0.f, a3 = 0.f;
        const float* HH = Hs + half * 16384;
        const float* WW = Wsr + half * 4096;
#pragma unroll 8
        for (int k = 0; k < 256; k++) {
            float4 h4 = ((const float4*)(HH + k * 64))[bg];
            float w = WW[k * 16 + c];
            a0 = fmaf(h4.x, w, a0);
            a1 = fmaf(h4.y, w, a1);
            a2 = fmaf(h4.z, w, a2);
            a3 = fmaf(h4.w, w, a3);
        }

        int b0 = bg * 4;
        if (half == 0) {
            size_t gbase = ((size_t)(t * BATCH + b0)) * G1N + gcol;
            sg[c * 64 + b0 + 0] = a0 + g_G1[gbase];
            sg[c * 64 + b0 + 1] = a1 + g_G1[gbase + G1N];
            sg[c * 64 + b0 + 2] = a2 + g_G1[gbase + 2 * (size_t)G1N];
            sg[c * 64 + b0 + 3] = a3 + g_G1[gbase + 3 * (size_t)G1N];
        }
        __syncthreads();
        if (half == 1) {
            sg[c * 64 + b0 + 0] += a0;
            sg[c * 64 + b0 + 1] += a1;
            sg[c * 64 + b0 + 2] += a2;
            sg[c * 64 + b0 + 3] += a3;
        }
        __syncthreads();

        if (tid < 256) {
            float gi = sigf(sg[(0 * 4 + u2) * 64 + bb]);
            float gf = sigf(sg[(1 * 4 + u2) * 64 + bb]);
            float gc = tanh_fast(sg[(2 * 4 + u2) * 64 + bb]);
            float go = sigf(sg[(3 * 4 + u2) * 64 + bb]);
            int jj = j0 + u2;
            creg = fmaf(gf, creg, gi * gc);
            float h = go * tanh_fast(creg);
            g_hT[rp ^ 1][jj * BATCH + bb] = h;
            g_hs1[((size_t)(t * BATCH + bb)) * H1 + jj] = h;
        }

        if (t < TSTEPS - 1) {
            __threadfence();          // release: drain h stores (gpu scope)
            __syncthreads();          // all threads fenced before arrive
            if (tid == 0) {
                atomicAdd(&g_bar, 1u);
                unsigned target = 128u * (unsigned)(t + 1);
                while (atomicAdd(&g_bar, 0u) < target) { }
            }
            __syncthreads();
            __threadfence();          // acquire: invalidate L1 for peer h loads
        }
    }
}

// ---------------- LSTM2: cluster of 8, per-source mbarrier handshake (R7 protocol) --------
__device__ __forceinline__ void mbar_wait_cluster(uint32_t mbar, uint32_t parity) {
    asm volatile(
        "{\n\t"
        ".reg .pred P;\n\t"
        "WAIT_%=:\n\t"
        "mbarrier.try_wait.parity.acquire.cluster.shared::cta.b64 P, [%0], %1, 0x989680;\n\t"
        "@P bra.uni DONE_%=;\n\t"
        "bra.uni WAIT_%=;\n\t"
        "DONE_%=:\n\t"
        "}" :: "r"(mbar), "r"(parity) : "memory");
}

__global__ void __cluster_dims__(8, 1, 1) __launch_bounds__(512, 1)
lstm2_kernel(const float* __restrict__ Whh2) {
    __shared__ __align__(16) float sh_h[2][H2];
    __shared__ float sg2[128];
    __shared__ __align__(8) unsigned long long mb[2][8];   // [buf][src CTA]

    int tid = threadIdx.x;
    uint32_t rank;
    asm("mov.u32 %0, %%cluster_ctarank;" : "=r"(rank));

    int lr = tid >> 2;   // gate row 0..127
    int kq = tid & 3;    // k quarter
    int g  = lr >> 5;    // gate 0=i 1=f 2=g 3=o
    int j  = lr & 31;
    int gr = g * H2 + (int)rank * 32 + j;

    // W row slice, pre-packed as f32x2 pairs
    unsigned long long w2[32];
    {
        const ulonglong2* wp = (const ulonglong2*)(Whh2 + (size_t)gr * H2 + kq * 64);
#pragma unroll
        for (int i = 0; i < 16; i++) {
            ulonglong2 v = wp[i];
            w2[2 * i] = v.x; w2[2 * i + 1] = v.y;
        }
    }

    if (tid < H2) sh_h[0][tid] = 0.0f;

    uint32_t mbb = (uint32_t)__cvta_generic_to_shared(&mb[0][0]);
    if (tid < 16) {
        uint32_t a = mbb + tid * 8u;
        asm volatile("mbarrier.init.shared.b64 [%0], %1;" :: "r"(a), "r"(4) : "memory");
    }
    __syncthreads();
    asm volatile("barrier.cluster.arrive.aligned;" ::: "memory");
    asm volatile("barrier.cluster.wait.aligned;" ::: "memory");

    // writer-lane precomputed remote addresses (lane -> one peer d, 8-float slot q)
    uint32_t rh[2], rm[2];
    uint32_t hb = (uint32_t)__cvta_generic_to_shared(&sh_h[0][0]);
    if (tid < 32) {
        int d = tid >> 2, q = tid & 3;
        uint32_t l0 = hb + (uint32_t)((int)rank * 32 + q * 8) * 4u;
        uint32_t l1 = l0 + H2 * 4u;
        uint32_t m0 = mbb + (uint32_t)(0 * 8 + (int)rank) * 8u;
        uint32_t m1 = mbb + (uint32_t)(1 * 8 + (int)rank) * 8u;
        asm("mapa.shared::cluster.u32 %0, %1, %2;" : "=r"(rh[0]) : "r"(l0), "r"(d));
        asm("mapa.shared::cluster.u32 %0, %1, %2;" : "=r"(rh[1]) : "r"(l1), "r"(d));
        asm("mapa.shared::cluster.u32 %0, %1, %2;" : "=r"(rm[0]) : "r"(m0), "r"(d));
        asm("mapa.shared::cluster.u32 %0, %1, %2;" : "=r"(rm[1]) : "r"(m1), "r"(d));
    }

    float c = 0.0f;
    float u_next = (kq == 0) ? __ldg(&g_G2[gr]) : 0.0f;
    int ph0 = 0, ph1 = 0;
    int wid = tid >> 5, lane = tid & 31;

    for (int r = 0; r < TB; r++) {
        int buf = r & 1;
        if (r > 0) {
            if (wid < 8) {
                if (lane == 0) {
                    uint32_t bar = mbb + (uint32_t)(buf * 8 + wid) * 8u;
                    mbar_wait_cluster(bar, (uint32_t)(buf ? ph1 : ph0));
                }
                __syncwarp();
            }
            if (buf) ph1 ^= 1; else ph0 ^= 1;
        }
        __syncthreads();

        float u = u_next;
        if (kq == 0 && r + 1 < TB) u_next = __ldg(&g_G2[(size_t)(r + 1) * G2N + gr]);

        const ulonglong2* hp = (const ulonglong2*)(&sh_h[buf][kq * 64]);
        unsigned long long acc01 = 0ull, acc23 = 0ull;
#pragma unroll
        for (int i = 0; i < 16; i++) {
            ulonglong2 hv = hp[i];
            asm("fma.rn.f32x2 %0, %1, %2, %3;" : "=l"(acc01) : "l"(w2[2 * i]), "l"(hv.x), "l"(acc01));
            asm("fma.rn.f32x2 %0, %1, %2, %3;" : "=l"(acc23) : "l"(w2[2 * i + 1]), "l"(hv.y), "l"(acc23));
        }
        float acc = (__uint_as_float((unsigned)acc01) + __uint_as_float((unsigned)(acc01 >> 32)))
                  + (__uint_as_float((unsigned)acc23) + __uint_as_float((unsigned)(acc23 >> 32)));
        acc += __shfl_xor_sync(0xffffffffu, acc, 1);
        acc += __shfl_xor_sync(0xffffffffu, acc, 2);

        if (kq == 0) {
            float pre = acc + u;
            sg2[lr] = (g == 2) ? tanh_fast(pre) : sigf(pre);
        }
        __syncthreads();

        int nb = buf ^ 1;
        if (tid < 32) {
            float gi = sg2[tid];
            float gf = sg2[32 + tid];
            float gc = sg2[64 + tid];
            float go = sg2[96 + tid];
            c = fmaf(gf, c, gi * gc);
            float h = go * tanh_fast(c);
            sh_h[nb][(int)rank * 32 + tid] = h;
            __syncwarp();
            int q = tid & 3;
            const float4* sp = (const float4*)(&sh_h[nb][(int)rank * 32 + q * 8]);
            float4 v0 = sp[0], v1 = sp[1];
            uint32_t dst = rh[nb];
            asm volatile("st.shared::cluster.v4.f32 [%0], {%1,%2,%3,%4};"
                         :: "r"(dst), "f"(v0.x), "f"(v0.y), "f"(v0.z), "f"(v0.w) : "memory");
            asm volatile("st.shared::cluster.v4.f32 [%0], {%1,%2,%3,%4};"
                         :: "r"(dst + 16u), "f"(v1.x), "f"(v1.y), "f"(v1.z), "f"(v1.w) : "memory");
            asm volatile("mbarrier.arrive.release.cluster.shared::cluster.b64 _, [%0];"
                         :: "r"(rm[nb]) : "memory");
        }
    }

    if (wid < 8) {
        if (lane == 0) {
            uint32_t bar = mbb + (uint32_t)(0 * 8 + wid) * 8u;
            mbar_wait_cluster(bar, (uint32_t)ph0);
        }
        __syncwarp();
    }
    __syncthreads();
    if (rank == 0 && tid < H2) g_hT2[tid] = sh_h[0][tid];

    asm volatile("barrier.cluster.arrive.aligned;" ::: "memory");
    asm volatile("barrier.cluster.wait.aligned;" ::: "memory");
}

// ---------------- tail MLP ----------------
__global__ void mlp_kernel(const float* __restrict__ W1, const float* __restrict__ b1,
                           const float* __restrict__ W2, const float* __restrict__ b2,
                           float* __restrict__ out) {
    __shared__ float emb[H2];
    __shared__ float o1[128];
    int tid = threadIdx.x;  // 128
    {
        float h0 = g_hT2[tid];
        float h1 = g_hT2[tid + 128];
        emb[tid]       = h0 + h0 * h0;
        emb[tid + 128] = h1 + h1 * h1;
    }
    __syncthreads();
    float s = b1[tid];
    const float* wrow = W1 + (size_t)tid * H2;
#pragma unroll 8
    for (int k = 0; k < H2; k++) s = fmaf(emb[k], wrow[k], s);
    o1[tid] = s;
    __syncthreads();
    if (tid < 10) {
        float s2 = b2[tid];
        const float* w2r = W2 + (size_t)tid * 128;
#pragma unroll 8
        for (int k = 0; k < 128; k++) s2 = fmaf(o1[k], w2r[k], s2);
        out[tid] = s2;
    }
}

extern "C" void kernel_launch(void* const* d_in, const int* in_sizes, int n_in,
                              void* d_out, int out_size) {
    const float* x     = (const float*)d_in[0];
    const float* W_ih1 = (const float*)d_in[1];
    const float* W_hh1 = (const float*)d_in[2];
    const float* b_ih1 = (const float*)d_in[3];
    const float* b_hh1 = (const float*)d_in[4];
    const float* W_ih2 = (const float*)d_in[5];
    const float* W_hh2 = (const float*)d_in[6];
    const float* b_ih2 = (const float*)d_in[7];
    const float* b_hh2 = (const float*)d_in[8];
    const float* W1    = (const float*)d_in[9];
    const float* b1    = (const float*)d_in[10];
    const float* W2    = (const float*)d_in[11];
    const float* b2    = (const float*)d_in[12];
    float* out = (float*)d_out;

    const int LSTM1_SMEM = (2 * 16384 + 2 * 4096 + 1024) * 4;   // 167936 B
    cudaFuncSetAttribute(lstm1_persist, cudaFuncAttributeMaxDynamicSharedMemorySize,
                         LSTM1_SMEM);

    zero_state<<<128, 256>>>();                                        // launch 0
    gemm64<0><<<dim3(G1N / 64, TB / 64), 256>>>(x, W_ih1, b_ih1, b_hh1);  // 1
    lstm1_persist<<<128, 512, LSTM1_SMEM>>>(W_hh1);                    // 2
    gemm64<1><<<dim3(G2N / 64, TB / 64), 256>>>(x, W_ih2, b_ih2, b_hh2);  // 3
    noop_kernel<<<1, 32>>>();                                          // 4
    lstm2_kernel<<<8, 512>>>(W_hh2);                                   // 5  <- ncu -s 5 -c 1
    mlp_kernel<<<1, 128>>>(W1, b1, W2, b2, out);                       // 6
}

// round 14
// speedup vs baseline: 1.2719x; 1.0559x over previous
#include <cuda_runtime.h>
#include <cuda_bf16.h>
#include <cstdint>

#define BATCH   64
#define TSTEPS  128
#define TB      8192
#define DIN     768
#define H1      512
#define G1N     2048
#define H2      256
#define G2N     1024

// ---------------- static device scratch (no allocations) ----------------
__device__ float g_G1[(size_t)TB * G1N];   // 64 MB
__device__ float g_G2[(size_t)TB * G2N];   // 32 MB
__device__ float g_hs1[(size_t)TB * H1];   // 16 MB
__device__ float g_hT[2][H1 * BATCH];      // h1 transposed [j][b], double-buffered
__device__ float g_hT2[H2];                // final LSTM2 hidden
__device__ unsigned g_bar;                 // lstm1 global barrier counter

__device__ __forceinline__ float sigf(float x) { return 1.0f / (1.0f + __expf(-x)); }
__device__ __forceinline__ float tanh_fast(float x) {
    float xc = fminf(fmaxf(x, -15.0f), 15.0f);
    float e = __expf(2.0f * xc);
    return __fdividef(e - 1.0f, e + 1.0f);
}

// ---------------- GEMM: C[M,N] = A[M,K] @ B[N,K]^T + bias1 + bias2 ----------------
template <int MODE>
__global__ void __launch_bounds__(256) gemm64(const float* __restrict__ A,
                                              const float* __restrict__ B,
                                              const float* __restrict__ bias1,
                                              const float* __restrict__ bias2) {
    constexpr int N = (MODE == 0) ? G1N : G2N;
    constexpr int K = (MODE == 0) ? DIN : H1;
    float* __restrict__ C = (MODE == 0) ? g_G1 : g_G2;
    const float* __restrict__ Ap = (MODE == 0) ? A : g_hs1;

    __shared__ float As[16][64];
    __shared__ float Bs[16][64];

    int tid = threadIdx.x;
    if (MODE == 0 && blockIdx.x == 0 && blockIdx.y == 0 && tid == 0) g_bar = 0u;

    int m0 = blockIdx.y * 64, n0 = blockIdx.x * 64;
    int tx = tid & 15, ty = tid >> 4;

    int la_m = tid & 63, la_k = (tid >> 6) * 4;
    int lb_n = tid >> 2, lb_k = (tid & 3) * 4;

    int r = m0 + la_m;
    size_t arow;
    if (MODE == 0) {
        int b = r & 63, t = r >> 6;
        arow = ((size_t)b * TSTEPS + t) * DIN;
    } else {
        arow = (size_t)r * K;
    }

    float acc[4][4];
#pragma unroll
    for (int i = 0; i < 4; i++)
#pragma unroll
        for (int j = 0; j < 4; j++) acc[i][j] = 0.0f;

    for (int kt = 0; kt < K; kt += 16) {
        float4 av = *(const float4*)(Ap + arow + kt + la_k);
        As[la_k + 0][la_m] = av.x;
        As[la_k + 1][la_m] = av.y;
        As[la_k + 2][la_m] = av.z;
        As[la_k + 3][la_m] = av.w;
        float4 bv = *(const float4*)(B + (size_t)(n0 + lb_n) * K + kt + lb_k);
        Bs[lb_k + 0][lb_n] = bv.x;
        Bs[lb_k + 1][lb_n] = bv.y;
        Bs[lb_k + 2][lb_n] = bv.z;
        Bs[lb_k + 3][lb_n] = bv.w;
        __syncthreads();
#pragma unroll
        for (int k = 0; k < 16; k++) {
            float4 a  = ((const float4*)As[k])[ty];
            float4 b4 = ((const float4*)Bs[k])[tx];
            acc[0][0] = fmaf(a.x, b4.x, acc[0][0]);
            acc[0][1] = fmaf(a.x, b4.y, acc[0][1]);
            acc[0][2] = fmaf(a.x, b4.z, acc[0][2]);
            acc[0][3] = fmaf(a.x, b4.w, acc[0][3]);
            acc[1][0] = fmaf(a.y, b4.x, acc[1][0]);
            acc[1][1] = fmaf(a.y, b4.y, acc[1][1]);
            acc[1][2] = fmaf(a.y, b4.z, acc[1][2]);
            acc[1][3] = fmaf(a.y, b4.w, acc[1][3]);
            acc[2][0] = fmaf(a.z, b4.x, acc[2][0]);
            acc[2][1] = fmaf(a.z, b4.y, acc[2][1]);
            acc[2][2] = fmaf(a.z, b4.z, acc[2][2]);
            acc[2][3] = fmaf(a.z, b4.w, acc[2][3]);
            acc[3][0] = fmaf(a.w, b4.x, acc[3][0]);
            acc[3][1] = fmaf(a.w, b4.y, acc[3][1]);
            acc[3][2] = fmaf(a.w, b4.z, acc[3][2]);
            acc[3][3] = fmaf(a.w, b4.w, acc[3][3]);
        }
        __syncthreads();
    }

    int coln = n0 + tx * 4;
    float bb0 = bias1[coln + 0] + bias2[coln + 0];
    float bb1 = bias1[coln + 1] + bias2[coln + 1];
    float bb2 = bias1[coln + 2] + bias2[coln + 2];
    float bb3 = bias1[coln + 3] + bias2[coln + 3];
#pragma unroll
    for (int i = 0; i < 4; i++) {
        int row = m0 + ty * 4 + i;
        float4 o;
        o.x = acc[i][0] + bb0;
        o.y = acc[i][1] + bb1;
        o.z = acc[i][2] + bb2;
        o.w = acc[i][3] + bb3;
        *(float4*)(C + (size_t)row * N + coln) = o;
    }
}

// ---------------- LSTM1: persistent, 128 blocks; load-based global barrier ----------------
#define WPAD 260      // padded weight row stride (floats)
__device__ __forceinline__ void gbar_sync(int tid, unsigned target) {
    __threadfence();              // release: drain h stores before arrive
    __syncthreads();
    if (tid == 0) {
        atomicAdd(&g_bar, 1u);
        unsigned v;
        do {
            asm volatile("ld.global.acquire.gpu.u32 %0, [%1];"
                         : "=r"(v) : "l"(&g_bar) : "memory");
            if (v >= target) break;
            __nanosleep(64);
        } while (true);
    }
    __syncthreads();
}

__global__ void __launch_bounds__(512) lstm1_persist(const float* __restrict__ Whh1) {
    extern __shared__ float dsm[];
    float* Hs  = dsm;                     // [2][16384]  128 KB
    float* Wsr = dsm + 32768;             // [2][16*WPAD] c-major, padded
    float* sg  = dsm + 32768 + 2 * 16 * WPAD;   // [16*64]

    int tid = threadIdx.x;
    int half = tid >> 8;       // k half: [half*256, half*256+256)
    int lt = tid & 255;
    int c  = lt & 15;          // local gate column 0..15
    int bg = lt >> 4;          // batch group 0..15
    int j0 = blockIdx.x * 4;
    int gg_ = c >> 2, u = c & 3;
    int gcol = gg_ * H1 + j0 + u;

    // zero g_hT[0] (32768 floats over 128 blocks x 512 thr)
    {
        int zid = blockIdx.x * 512 + tid;
        if (zid < H1 * BATCH) g_hT[0][zid] = 0.0f;
    }

    // resident weights, c-major padded: Wsr[half][wc*WPAD + k_local]
    {
        int wc = lt & 15, wk4 = lt >> 4;
        int wg = wc >> 2, wu = wc & 3;
        float* W = Wsr + half * 16 * WPAD;
#pragma unroll
        for (int kk = 0; kk < 4; kk++) {
            int ktl = kk * 64 + wk4 * 4;
            float4 wv = *(const float4*)(Whh1 + (size_t)(wg * H1 + j0 + wu) * H1 + half * 256 + ktl);
            *(float4*)(W + wc * WPAD + ktl) = wv;
        }
    }

    gbar_sync(tid, 128u);   // zeroing visible cluster-wide

    int u2 = tid >> 6, bb = tid & 63;
    float creg = 0.0f;

    for (int t = 0; t < TSTEPS; t++) {
        int rp = t & 1;
        // stage this half's h: 4096 float4s, L1-bypassed (fresh from peers via L2)
        {
            const float4* s4 = (const float4*)(g_hT[rp] + half * 16384);
            float4* d4 = (float4*)(Hs + half * 16384);
#pragma unroll
            for (int i = 0; i < 16; i++) d4[lt + i * 256] = __ldcg(&s4[lt + i * 256]);
        }
        __syncthreads();

        float a0 = 0.f, a1 = 0.f, a2 = 0.f, a3 = 0.f;
        const float* HH = Hs + half * 16384;
        const float* WR = Wsr + half * 16 * WPAD + c * WPAD;
#pragma unroll 8
        for (int k4 = 0; k4 < 64; k4++) {
            float4 w4 = *(const float4*)(WR + k4 * 4);
            int k = k4 * 4;
            float4 h0 = ((const float4*)(HH + (k + 0) * 64))[bg];
            a0 = fmaf(h0.x, w4.x, a0); a1 = fmaf(h0.y, w4.x, a1);
            a2 = fmaf(h0.z, w4.x, a2); a3 = fmaf(h0.w, w4.x, a3);
            float4 h1 = ((const float4*)(HH + (k + 1) * 64))[bg];
            a0 = fmaf(h1.x, w4.y, a0); a1 = fmaf(h1.y, w4.y, a1);
            a2 = fmaf(h1.z, w4.y, a2); a3 = fmaf(h1.w, w4.y, a3);
            float4 h2 = ((const float4*)(HH + (k + 2) * 64))[bg];
            a0 = fmaf(h2.x, w4.z, a0); a1 = fmaf(h2.y, w4.z, a1);
            a2 = fmaf(h2.z, w4.z, a2); a3 = fmaf(h2.w, w4.z, a3);
            float4 h3 = ((const float4*)(HH + (k + 3) * 64))[bg];
            a0 = fmaf(h3.x, w4.w, a0); a1 = fmaf(h3.y, w4.w, a1);
            a2 = fmaf(h3.z, w4.w, a2); a3 = fmaf(h3.w, w4.w, a3);
        }

        int b0 = bg * 4;
        if (half == 0) {
            size_t gbase = ((size_t)(t * BATCH + b0)) * G1N + gcol;
            sg[c * 64 + b0 + 0] = a0 + g_G1[gbase];
            sg[c * 64 + b0 + 1] = a1 + g_G1[gbase + G1N];
            sg[c * 64 + b0 + 2] = a2 + g_G1[gbase + 2 * (size_t)G1N];
            sg[c * 64 + b0 + 3] = a3 + g_G1[gbase + 3 * (size_t)G1N];
        }
        __syncthreads();
        if (half == 1) {
            sg[c * 64 + b0 + 0] += a0;
            sg[c * 64 + b0 + 1] += a1;
            sg[c * 64 + b0 + 2] += a2;
            sg[c * 64 + b0 + 3] += a3;
        }
        __syncthreads();

        if (tid < 256) {
            float gi = sigf(sg[(0 * 4 + u2) * 64 + bb]);
            float gf = sigf(sg[(1 * 4 + u2) * 64 + bb]);
            float gc = tanh_fast(sg[(2 * 4 + u2) * 64 + bb]);
            float go = sigf(sg[(3 * 4 + u2) * 64 + bb]);
            int jj = j0 + u2;
            creg = fmaf(gf, creg, gi * gc);
            float h = go * tanh_fast(creg);
            g_hT[rp ^ 1][jj * BATCH + bb] = h;
            g_hs1[((size_t)(t * BATCH + bb)) * H1 + jj] = h;
        }

        if (t < TSTEPS - 1) gbar_sync(tid, 128u * (unsigned)(t + 2));
    }
}

// ---------------- LSTM2: cluster of 8, per-source mbarrier handshake (R7 protocol) --------
__device__ __forceinline__ void mbar_wait_cluster(uint32_t mbar, uint32_t parity) {
    asm volatile(
        "{\n\t"
        ".reg .pred P;\n\t"
        "WAIT_%=:\n\t"
        "mbarrier.try_wait.parity.acquire.cluster.shared::cta.b64 P, [%0], %1, 0x989680;\n\t"
        "@P bra.uni DONE_%=;\n\t"
        "bra.uni WAIT_%=;\n\t"
        "DONE_%=:\n\t"
        "}" :: "r"(mbar), "r"(parity) : "memory");
}

__global__ void __cluster_dims__(8, 1, 1) __launch_bounds__(512, 1)
lstm2_kernel(const float* __restrict__ Whh2) {
    __shared__ __align__(16) float sh_h[2][H2];
    __shared__ float sg2[128];
    __shared__ __align__(8) unsigned long long mb[2][8];   // [buf][src CTA]

    int tid = threadIdx.x;
    uint32_t rank;
    asm("mov.u32 %0, %%cluster_ctarank;" : "=r"(rank));

    int lr = tid >> 2;   // gate row 0..127
    int kq = tid & 3;    // k quarter
    int g  = lr >> 5;    // gate 0=i 1=f 2=g 3=o
    int j  = lr & 31;
    int gr = g * H2 + (int)rank * 32 + j;

    unsigned long long w2[32];
    {
        const ulonglong2* wp = (const ulonglong2*)(Whh2 + (size_t)gr * H2 + kq * 64);
#pragma unroll
        for (int i = 0; i < 16; i++) {
            ulonglong2 v = wp[i];
            w2[2 * i] = v.x; w2[2 * i + 1] = v.y;
        }
    }

    if (tid < H2) sh_h[0][tid] = 0.0f;

    uint32_t mbb = (uint32_t)__cvta_generic_to_shared(&mb[0][0]);
    if (tid < 16) {
        uint32_t a = mbb + tid * 8u;
        asm volatile("mbarrier.init.shared.b64 [%0], %1;" :: "r"(a), "r"(4) : "memory");
    }
    __syncthreads();
    asm volatile("barrier.cluster.arrive.aligned;" ::: "memory");
    asm volatile("barrier.cluster.wait.aligned;" ::: "memory");

    uint32_t rh[2], rm[2];
    uint32_t hb = (uint32_t)__cvta_generic_to_shared(&sh_h[0][0]);
    if (tid < 32) {
        int d = tid >> 2, q = tid & 3;
        uint32_t l0 = hb + (uint32_t)((int)rank * 32 + q * 8) * 4u;
        uint32_t l1 = l0 + H2 * 4u;
        uint32_t m0 = mbb + (uint32_t)(0 * 8 + (int)rank) * 8u;
        uint32_t m1 = mbb + (uint32_t)(1 * 8 + (int)rank) * 8u;
        asm("mapa.shared::cluster.u32 %0, %1, %2;" : "=r"(rh[0]) : "r"(l0), "r"(d));
        asm("mapa.shared::cluster.u32 %0, %1, %2;" : "=r"(rh[1]) : "r"(l1), "r"(d));
        asm("mapa.shared::cluster.u32 %0, %1, %2;" : "=r"(rm[0]) : "r"(m0), "r"(d));
        asm("mapa.shared::cluster.u32 %0, %1, %2;" : "=r"(rm[1]) : "r"(m1), "r"(d));
    }

    float c = 0.0f;
    float u_next = (kq == 0) ? __ldg(&g_G2[gr]) : 0.0f;
    int ph0 = 0, ph1 = 0;
    int wid = tid >> 5, lane = tid & 31;

    for (int r = 0; r < TB; r++) {
        int buf = r & 1;
        if (r > 0) {
            if (wid < 8) {
                if (lane == 0) {
                    uint32_t bar = mbb + (uint32_t)(buf * 8 + wid) * 8u;
                    mbar_wait_cluster(bar, (uint32_t)(buf ? ph1 : ph0));
                }
                __syncwarp();
            }
            if (buf) ph1 ^= 1; else ph0 ^= 1;
        }
        __syncthreads();

        float u = u_next;
        if (kq == 0 && r + 1 < TB) u_next = __ldg(&g_G2[(size_t)(r + 1) * G2N + gr]);

        const ulonglong2* hp = (const ulonglong2*)(&sh_h[buf][kq * 64]);
        unsigned long long acc01 = 0ull, acc23 = 0ull;
#pragma unroll
        for (int i = 0; i < 16; i++) {
            ulonglong2 hv = hp[i];
            asm("fma.rn.f32x2 %0, %1, %2, %3;" : "=l"(acc01) : "l"(w2[2 * i]), "l"(hv.x), "l"(acc01));
            asm("fma.rn.f32x2 %0, %1, %2, %3;" : "=l"(acc23) : "l"(w2[2 * i + 1]), "l"(hv.y), "l"(acc23));
        }
        float acc = (__uint_as_float((unsigned)acc01) + __uint_as_float((unsigned)(acc01 >> 32)))
                  + (__uint_as_float((unsigned)acc23) + __uint_as_float((unsigned)(acc23 >> 32)));
        acc += __shfl_xor_sync(0xffffffffu, acc, 1);
        acc += __shfl_xor_sync(0xffffffffu, acc, 2);

        if (kq == 0) {
            float pre = acc + u;
            sg2[lr] = (g == 2) ? tanh_fast(pre) : sigf(pre);
        }
        __syncthreads();

        int nb = buf ^ 1;
        if (tid < 32) {
            float gi = sg2[tid];
            float gf = sg2[32 + tid];
            float gc = sg2[64 + tid];
            float go = sg2[96 + tid];
            c = fmaf(gf, c, gi * gc);
            float h = go * tanh_fast(c);
            sh_h[nb][(int)rank * 32 + tid] = h;
            __syncwarp();
            int q = tid & 3;
            const float4* sp = (const float4*)(&sh_h[nb][(int)rank * 32 + q * 8]);
            float4 v0 = sp[0], v1 = sp[1];
            uint32_t dst = rh[nb];
            asm volatile("st.shared::cluster.v4.f32 [%0], {%1,%2,%3,%4};"
                         :: "r"(dst), "f"(v0.x), "f"(v0.y), "f"(v0.z), "f"(v0.w) : "memory");
            asm volatile("st.shared::cluster.v4.f32 [%0], {%1,%2,%3,%4};"
                         :: "r"(dst + 16u), "f"(v1.x), "f"(v1.y), "f"(v1.z), "f"(v1.w) : "memory");
            asm volatile("mbarrier.arrive.release.cluster.shared::cluster.b64 _, [%0];"
                         :: "r"(rm[nb]) : "memory");
        }
    }

    if (wid < 8) {
        if (lane == 0) {
            uint32_t bar = mbb + (uint32_t)(0 * 8 + wid) * 8u;
            mbar_wait_cluster(bar, (uint32_t)ph0);
        }
        __syncwarp();
    }
    __syncthreads();
    if (rank == 0 && tid < H2) g_hT2[tid] = sh_h[0][tid];

    asm volatile("barrier.cluster.arrive.aligned;" ::: "memory");
    asm volatile("barrier.cluster.wait.aligned;" ::: "memory");
}

// ---------------- tail MLP ----------------
__global__ void mlp_kernel(const float* __restrict__ W1, const float* __restrict__ b1,
                           const float* __restrict__ W2, const float* __restrict__ b2,
                           float* __restrict__ out) {
    __shared__ float emb[H2];
    __shared__ float o1[128];
    int tid = threadIdx.x;  // 128
    {
        float h0 = g_hT2[tid];
        float h1 = g_hT2[tid + 128];
        emb[tid]       = h0 + h0 * h0;
        emb[tid + 128] = h1 + h1 * h1;
    }
    __syncthreads();
    float s = b1[tid];
    const float* wrow = W1 + (size_t)tid * H2;
#pragma unroll 8
    for (int k = 0; k < H2; k++) s = fmaf(emb[k], wrow[k], s);
    o1[tid] = s;
    __syncthreads();
    if (tid < 10) {
        float s2 = b2[tid];
        const float* w2r = W2 + (size_t)tid * 128;
#pragma unroll 8
        for (int k = 0; k < 128; k++) s2 = fmaf(o1[k], w2r[k], s2);
        out[tid] = s2;
    }
}

extern "C" void kernel_launch(void* const* d_in, const int* in_sizes, int n_in,
                              void* d_out, int out_size) {
    const float* x     = (const float*)d_in[0];
    const float* W_ih1 = (const float*)d_in[1];
    const float* W_hh1 = (const float*)d_in[2];
    const float* b_ih1 = (const float*)d_in[3];
    const float* b_hh1 = (const float*)d_in[4];
    const float* W_ih2 = (const float*)d_in[5];
    const float* W_hh2 = (const float*)d_in[6];
    const float* b_ih2 = (const float*)d_in[7];
    const float* b_hh2 = (const float*)d_in[8];
    const float* W1    = (const float*)d_in[9];
    const float* b1    = (const float*)d_in[10];
    const float* W2    = (const float*)d_in[11];
    const float* b2    = (const float*)d_in[12];
    float* out = (float*)d_out;

    const int LSTM1_SMEM = (32768 + 2 * 16 * WPAD + 1024) * 4;   // 168448 B
    cudaFuncSetAttribute(lstm1_persist, cudaFuncAttributeMaxDynamicSharedMemorySize,
                         LSTM1_SMEM);

    gemm64<0><<<dim3(G1N / 64, TB / 64), 256>>>(x, W_ih1, b_ih1, b_hh1);  // 0 (+g_bar reset)
    lstm1_persist<<<128, 512, LSTM1_SMEM>>>(W_hh1);                       // 1
    gemm64<1><<<dim3(G2N / 64, TB / 64), 256>>>(x, W_ih2, b_ih2, b_hh2);  // 2
    lstm2_kernel<<<8, 512>>>(W_hh2);                                      // 3 <- hoped ncu slot
    mlp_kernel<<<1, 128>>>(W1, b1, W2, b2, out);                          // 4
}

// round 16
// speedup vs baseline: 1.7713x; 1.3926x over previous
#include <cuda_runtime.h>
#include <cuda_bf16.h>
#include <cstdint>

#define BATCH   64
#define TSTEPS  128
#define TB      8192
#define DIN     768
#define H1      512
#define G1N     2048
#define H2      256
#define G2N     1024

// ---------------- static device scratch (no allocations) ----------------
__device__ float g_G1[(size_t)TB * G1N];   // 64 MB
__device__ float g_G2[(size_t)TB * G2N];   // 32 MB
__device__ float g_hs1[(size_t)TB * H1];   // 16 MB
__device__ float g_hT[2][H1 * BATCH];      // h1 transposed [j][b], double-buffered
__device__ float g_hT2[H2];                // final LSTM2 hidden
__device__ unsigned g_bar;                 // lstm1 global barrier counter

__device__ __forceinline__ float sigf(float x) { return 1.0f / (1.0f + __expf(-x)); }
__device__ __forceinline__ float tanh_fast(float x) {
    float xc = fminf(fmaxf(x, -15.0f), 15.0f);
    float e = __expf(2.0f * xc);
    return __fdividef(e - 1.0f, e + 1.0f);
}

// ---------------- GEMM: C[M,N] = A[M,K] @ B[N,K]^T + bias1 + bias2 ----------------
template <int MODE>
__global__ void __launch_bounds__(256) gemm64(const float* __restrict__ A,
                                              const float* __restrict__ B,
                                              const float* __restrict__ bias1,
                                              const float* __restrict__ bias2) {
    constexpr int N = (MODE == 0) ? G1N : G2N;
    constexpr int K = (MODE == 0) ? DIN : H1;
    float* __restrict__ C = (MODE == 0) ? g_G1 : g_G2;
    const float* __restrict__ Ap = (MODE == 0) ? A : g_hs1;

    __shared__ float As[16][64];
    __shared__ float Bs[16][64];

    int tid = threadIdx.x;
    if (MODE == 0 && blockIdx.x == 0 && blockIdx.y == 0 && tid == 0) g_bar = 0u;

    int m0 = blockIdx.y * 64, n0 = blockIdx.x * 64;
    int tx = tid & 15, ty = tid >> 4;

    int la_m = tid & 63, la_k = (tid >> 6) * 4;
    int lb_n = tid >> 2, lb_k = (tid & 3) * 4;

    int r = m0 + la_m;
    size_t arow;
    if (MODE == 0) {
        int b = r & 63, t = r >> 6;
        arow = ((size_t)b * TSTEPS + t) * DIN;
    } else {
        arow = (size_t)r * K;
    }

    float acc[4][4];
#pragma unroll
    for (int i = 0; i < 4; i++)
#pragma unroll
        for (int j = 0; j < 4; j++) acc[i][j] = 0.0f;

    for (int kt = 0; kt < K; kt += 16) {
        float4 av = *(const float4*)(Ap + arow + kt + la_k);
        As[la_k + 0][la_m] = av.x;
        As[la_k + 1][la_m] = av.y;
        As[la_k + 2][la_m] = av.z;
        As[la_k + 3][la_m] = av.w;
        float4 bv = *(const float4*)(B + (size_t)(n0 + lb_n) * K + kt + lb_k);
        Bs[lb_k + 0][lb_n] = bv.x;
        Bs[lb_k + 1][lb_n] = bv.y;
        Bs[lb_k + 2][lb_n] = bv.z;
        Bs[lb_k + 3][lb_n] = bv.w;
        __syncthreads();
#pragma unroll
        for (int k = 0; k < 16; k++) {
            float4 a  = ((const float4*)As[k])[ty];
            float4 b4 = ((const float4*)Bs[k])[tx];
            acc[0][0] = fmaf(a.x, b4.x, acc[0][0]);
            acc[0][1] = fmaf(a.x, b4.y, acc[0][1]);
            acc[0][2] = fmaf(a.x, b4.z, acc[0][2]);
            acc[0][3] = fmaf(a.x, b4.w, acc[0][3]);
            acc[1][0] = fmaf(a.y, b4.x, acc[1][0]);
            acc[1][1] = fmaf(a.y, b4.y, acc[1][1]);
            acc[1][2] = fmaf(a.y, b4.z, acc[1][2]);
            acc[1][3] = fmaf(a.y, b4.w, acc[1][3]);
            acc[2][0] = fmaf(a.z, b4.x, acc[2][0]);
            acc[2][1] = fmaf(a.z, b4.y, acc[2][1]);
            acc[2][2] = fmaf(a.z, b4.z, acc[2][2]);
            acc[2][3] = fmaf(a.z, b4.w, acc[2][3]);
            acc[3][0] = fmaf(a.w, b4.x, acc[3][0]);
            acc[3][1] = fmaf(a.w, b4.y, acc[3][1]);
            acc[3][2] = fmaf(a.w, b4.z, acc[3][2]);
            acc[3][3] = fmaf(a.w, b4.w, acc[3][3]);
        }
        __syncthreads();
    }

    int coln = n0 + tx * 4;
    float bb0 = bias1[coln + 0] + bias2[coln + 0];
    float bb1 = bias1[coln + 1] + bias2[coln + 1];
    float bb2 = bias1[coln + 2] + bias2[coln + 2];
    float bb3 = bias1[coln + 3] + bias2[coln + 3];
#pragma unroll
    for (int i = 0; i < 4; i++) {
        int row = m0 + ty * 4 + i;
        float4 o;
        o.x = acc[i][0] + bb0;
        o.y = acc[i][1] + bb1;
        o.z = acc[i][2] + bb2;
        o.w = acc[i][3] + bb3;
        *(float4*)(C + (size_t)row * N + coln) = o;
    }
}

// ---------------- LSTM1: persistent, 128 blocks; load-based global barrier ----------------
#define WPAD 260      // padded weight row stride (floats)
__device__ __forceinline__ void gbar_sync(int tid, unsigned target) {
    __threadfence();              // release: drain h stores before arrive
    __syncthreads();
    if (tid == 0) {
        atomicAdd(&g_bar, 1u);
        unsigned v;
        do {
            asm volatile("ld.global.acquire.gpu.u32 %0, [%1];"
                         : "=r"(v) : "l"(&g_bar) : "memory");
            if (v >= target) break;
            __nanosleep(64);
        } while (true);
    }
    __syncthreads();
}

__global__ void __launch_bounds__(512) lstm1_persist(const float* __restrict__ Whh1) {
    extern __shared__ float dsm[];
    float* Hs  = dsm;                     // [2][16384]  128 KB
    float* Wsr = dsm + 32768;             // [2][16*WPAD] c-major, padded
    float* sg  = dsm + 32768 + 2 * 16 * WPAD;   // [16*64]

    int tid = threadIdx.x;
    int half = tid >> 8;       // k half: [half*256, half*256+256)
    int lt = tid & 255;
    int c  = lt & 15;          // local gate column 0..15
    int bg = lt >> 4;          // batch group 0..15
    int j0 = blockIdx.x * 4;
    int gg_ = c >> 2, u = c & 3;
    int gcol = gg_ * H1 + j0 + u;

    // zero g_hT[0]
    {
        int zid = blockIdx.x * 512 + tid;
        if (zid < H1 * BATCH) g_hT[0][zid] = 0.0f;
    }

    // resident weights, c-major padded: Wsr[half][wc*WPAD + k_local]
    {
        int wc = lt & 15, wk4 = lt >> 4;
        int wg = wc >> 2, wu = wc & 3;
        float* W = Wsr + half * 16 * WPAD;
#pragma unroll
        for (int kk = 0; kk < 4; kk++) {
            int ktl = kk * 64 + wk4 * 4;
            float4 wv = *(const float4*)(Whh1 + (size_t)(wg * H1 + j0 + wu) * H1 + half * 256 + ktl);
            *(float4*)(W + wc * WPAD + ktl) = wv;
        }
    }

    gbar_sync(tid, 128u);   // zeroing visible

    int u2 = tid >> 6, bb = tid & 63;
    float creg = 0.0f;

    for (int t = 0; t < TSTEPS; t++) {
        int rp = t & 1;
        {
            const float4* s4 = (const float4*)(g_hT[rp] + half * 16384);
            float4* d4 = (float4*)(Hs + half * 16384);
#pragma unroll
            for (int i = 0; i < 16; i++) d4[lt + i * 256] = __ldcg(&s4[lt + i * 256]);
        }
        __syncthreads();

        float a0 = 0.f, a1 = 0.f, a2 = 0.f, a3 = 0.f;
        const float* HH = Hs + half * 16384;
        const float* WR = Wsr + half * 16 * WPAD + c * WPAD;
#pragma unroll 8
        for (int k4 = 0; k4 < 64; k4++) {
            float4 w4 = *(const float4*)(WR + k4 * 4);
            int k = k4 * 4;
            float4 h0 = ((const float4*)(HH + (k + 0) * 64))[bg];
            a0 = fmaf(h0.x, w4.x, a0); a1 = fmaf(h0.y, w4.x, a1);
            a2 = fmaf(h0.z, w4.x, a2); a3 = fmaf(h0.w, w4.x, a3);
            float4 h1 = ((const float4*)(HH + (k + 1) * 64))[bg];
            a0 = fmaf(h1.x, w4.y, a0); a1 = fmaf(h1.y, w4.y, a1);
            a2 = fmaf(h1.z, w4.y, a2); a3 = fmaf(h1.w, w4.y, a3);
            float4 h2 = ((const float4*)(HH + (k + 2) * 64))[bg];
            a0 = fmaf(h2.x, w4.z, a0); a1 = fmaf(h2.y, w4.z, a1);
            a2 = fmaf(h2.z, w4.z, a2); a3 = fmaf(h2.w, w4.z, a3);
            float4 h3 = ((const float4*)(HH + (k + 3) * 64))[bg];
            a0 = fmaf(h3.x, w4.w, a0); a1 = fmaf(h3.y, w4.w, a1);
            a2 = fmaf(h3.z, w4.w, a2); a3 = fmaf(h3.w, w4.w, a3);
        }

        int b0 = bg * 4;
        if (half == 0) {
            size_t gbase = ((size_t)(t * BATCH + b0)) * G1N + gcol;
            sg[c * 64 + b0 + 0] = a0 + g_G1[gbase];
            sg[c * 64 + b0 + 1] = a1 + g_G1[gbase + G1N];
            sg[c * 64 + b0 + 2] = a2 + g_G1[gbase + 2 * (size_t)G1N];
            sg[c * 64 + b0 + 3] = a3 + g_G1[gbase + 3 * (size_t)G1N];
        }
        __syncthreads();
        if (half == 1) {
            sg[c * 64 + b0 + 0] += a0;
            sg[c * 64 + b0 + 1] += a1;
            sg[c * 64 + b0 + 2] += a2;
            sg[c * 64 + b0 + 3] += a3;
        }
        __syncthreads();

        if (tid < 256) {
            float gi = sigf(sg[(0 * 4 + u2) * 64 + bb]);
            float gf = sigf(sg[(1 * 4 + u2) * 64 + bb]);
            float gc = tanh_fast(sg[(2 * 4 + u2) * 64 + bb]);
            float go = sigf(sg[(3 * 4 + u2) * 64 + bb]);
            int jj = j0 + u2;
            creg = fmaf(gf, creg, gi * gc);
            float h = go * tanh_fast(creg);
            g_hT[rp ^ 1][jj * BATCH + bb] = h;
            g_hs1[((size_t)(t * BATCH + bb)) * H1 + jj] = h;
        }

        if (t < TSTEPS - 1) gbar_sync(tid, 128u * (unsigned)(t + 2));
    }
}

// ---------------- LSTM2: cluster of 8, POLLING waits + warp-local gates ----------------
// No sleep: mbarrier.test_wait spin. One count-8 barrier per buffer. One syncthreads/step.
__device__ __forceinline__ void mbar_poll_cluster(uint32_t mbar, uint32_t parity) {
    asm volatile(
        "{\n\t"
        ".reg .pred P;\n\t"
        "POLL_%=:\n\t"
        "mbarrier.test_wait.parity.acquire.cluster.shared::cta.b64 P, [%0], %1;\n\t"
        "@P bra.uni DONE_%=;\n\t"
        "bra.uni POLL_%=;\n\t"
        "DONE_%=:\n\t"
        "}" :: "r"(mbar), "r"(parity) : "memory");
}

__global__ void __cluster_dims__(8, 1, 1) __launch_bounds__(512, 1)
lstm2_kernel(const float* __restrict__ Whh2) {
    __shared__ __align__(16) float sh_h[2][H2];     // replicated h, double-buffered
    __shared__ __align__(16) float sh_stage[32];    // this CTA's 32 new h values
    __shared__ __align__(8) unsigned long long mb[2];  // [buf], count=8 (one arrive/source)

    int tid = threadIdx.x;
    int w = tid >> 5, l = tid & 31;
    uint32_t rank;
    asm("mov.u32 %0, %%cluster_ctarank;" : "=r"(rank));

    // warp-local mapping: warp w owns units {2w, 2w+1}
    int j  = 2 * w + (l & 1);     // unit within CTA slice
    int kq = (l >> 1) & 3;        // k quarter
    int g  = l >> 3;              // gate 0=i 1=f 2=g 3=o
    int gr = g * H2 + (int)rank * 32 + j;
    bool isU = ((l & 6) == 0);    // kq==0 lanes

    // weights: 64 floats of row gr, quarter kq, packed f32x2
    unsigned long long w2[32];
    {
        const ulonglong2* wp = (const ulonglong2*)(Whh2 + (size_t)gr * H2 + kq * 64);
#pragma unroll
        for (int i = 0; i < 16; i++) {
            ulonglong2 v = wp[i];
            w2[2 * i] = v.x; w2[2 * i + 1] = v.y;
        }
    }

    if (tid < H2) sh_h[0][tid] = 0.0f;
    uint32_t mbb = (uint32_t)__cvta_generic_to_shared(&mb[0]);
    if (tid < 2) {
        uint32_t a = mbb + (uint32_t)tid * 8u;
        asm volatile("mbarrier.init.shared.b64 [%0], %1;" :: "r"(a), "r"(8) : "memory");
    }
    __syncthreads();
    asm volatile("barrier.cluster.arrive.aligned;" ::: "memory");
    asm volatile("barrier.cluster.wait.aligned;" ::: "memory");

    // writer warp (warp 0) lanes 0-7: lane d owns peer d; ship full 32-float slice
    uint32_t rh[2], rm[2];
    uint32_t hb = (uint32_t)__cvta_generic_to_shared(&sh_h[0][0]);
    if (w == 0 && l < 8) {
        int d = l;
        uint32_t l0 = hb + (uint32_t)((int)rank * 32) * 4u;        // buf0 slice base
        uint32_t l1 = l0 + H2 * 4u;                                // buf1 slice base
        asm("mapa.shared::cluster.u32 %0, %1, %2;" : "=r"(rh[0]) : "r"(l0), "r"(d));
        asm("mapa.shared::cluster.u32 %0, %1, %2;" : "=r"(rh[1]) : "r"(l1), "r"(d));
        asm("mapa.shared::cluster.u32 %0, %1, %2;" : "=r"(rm[0]) : "r"(mbb), "r"(d));
        asm("mapa.shared::cluster.u32 %0, %1, %2;" : "=r"(rm[1]) : "r"(mbb + 8u), "r"(d));
    }
    uint32_t stg = (uint32_t)__cvta_generic_to_shared(&sh_stage[0]);

    float c = 0.0f;
    float u_next = isU ? __ldg(&g_G2[gr]) : 0.0f;
    uint32_t ph[2] = {0u, 0u};

    for (int r = 0; r < TB; r++) {
        int buf = r & 1;
        if (r > 0) {
            if (l == 0) mbar_poll_cluster(mbb + (uint32_t)buf * 8u, ph[buf]);
            __syncwarp();
            ph[buf] ^= 1u;
        }

        float u = u_next;
        if (isU && r + 1 < TB) u_next = __ldg(&g_G2[(size_t)(r + 1) * G2N + gr]);

        const ulonglong2* hp = (const ulonglong2*)(&sh_h[buf][kq * 64]);
        unsigned long long acc01 = 0ull, acc23 = 0ull;
#pragma unroll
        for (int i = 0; i < 16; i++) {
            ulonglong2 hv = hp[i];
            asm("fma.rn.f32x2 %0, %1, %2, %3;" : "=l"(acc01) : "l"(w2[2 * i]), "l"(hv.x), "l"(acc01));
            asm("fma.rn.f32x2 %0, %1, %2, %3;" : "=l"(acc23) : "l"(w2[2 * i + 1]), "l"(hv.y), "l"(acc23));
        }
        float acc = (__uint_as_float((unsigned)acc01) + __uint_as_float((unsigned)(acc01 >> 32)))
                  + (__uint_as_float((unsigned)acc23) + __uint_as_float((unsigned)(acc23 >> 32)));
        acc += __shfl_xor_sync(0xffffffffu, acc, 2);   // reduce kq (lane bits 1-2)
        acc += __shfl_xor_sync(0xffffffffu, acc, 4);

        float act = 0.0f;
        if (isU) {
            float pre = acc + u;
            act = (g == 2) ? tanh_fast(pre) : sigf(pre);
        }
        int jb = l & 1;
        float gi = __shfl_sync(0xffffffffu, act, jb);
        float gf = __shfl_sync(0xffffffffu, act, 8 | jb);
        float gg = __shfl_sync(0xffffffffu, act, 16 | jb);
        float go = __shfl_sync(0xffffffffu, act, 24 | jb);

        c = fmaf(gf, c, gi * gg);          // redundant across lanes sharing unit j
        float h = go * tanh_fast(c);

        float h0 = __shfl_sync(0xffffffffu, h, 0);   // unit 2w
        float h1 = __shfl_sync(0xffffffffu, h, 1);   // unit 2w+1

        if (l == 0) {
            unsigned long long hv = ((unsigned long long)__float_as_uint(h1) << 32)
                                  | (unsigned long long)__float_as_uint(h0);
            asm volatile("st.shared.b64 [%0], %1;" :: "r"(stg + (uint32_t)(w * 8)), "l"(hv) : "memory");
        }
        __syncthreads();   // all 32 h staged; also closes WAR on sh_h[buf] before peers overwrite

        int nb = buf ^ 1;
        if (w == 0 && l < 8) {
            // read full 32-float stage (broadcast LDS) and ship to peer l
            float4 s0 = *(const float4*)(&sh_stage[0]);
            float4 s1 = *(const float4*)(&sh_stage[4]);
            float4 s2 = *(const float4*)(&sh_stage[8]);
            float4 s3 = *(const float4*)(&sh_stage[12]);
            float4 s4 = *(const float4*)(&sh_stage[16]);
            float4 s5 = *(const float4*)(&sh_stage[20]);
            float4 s6 = *(const float4*)(&sh_stage[24]);
            float4 s7 = *(const float4*)(&sh_stage[28]);
            uint32_t dst = rh[nb];
            asm volatile("st.shared::cluster.v4.f32 [%0], {%1,%2,%3,%4};"
                         :: "r"(dst +   0u), "f"(s0.x), "f"(s0.y), "f"(s0.z), "f"(s0.w) : "memory");
            asm volatile("st.shared::cluster.v4.f32 [%0], {%1,%2,%3,%4};"
                         :: "r"(dst +  16u), "f"(s1.x), "f"(s1.y), "f"(s1.z), "f"(s1.w) : "memory");
            asm volatile("st.shared::cluster.v4.f32 [%0], {%1,%2,%3,%4};"
                         :: "r"(dst +  32u), "f"(s2.x), "f"(s2.y), "f"(s2.z), "f"(s2.w) : "memory");
            asm volatile("st.shared::cluster.v4.f32 [%0], {%1,%2,%3,%4};"
                         :: "r"(dst +  48u), "f"(s3.x), "f"(s3.y), "f"(s3.z), "f"(s3.w) : "memory");
            asm volatile("st.shared::cluster.v4.f32 [%0], {%1,%2,%3,%4};"
                         :: "r"(dst +  64u), "f"(s4.x), "f"(s4.y), "f"(s4.z), "f"(s4.w) : "memory");
            asm volatile("st.shared::cluster.v4.f32 [%0], {%1,%2,%3,%4};"
                         :: "r"(dst +  80u), "f"(s5.x), "f"(s5.y), "f"(s5.z), "f"(s5.w) : "memory");
            asm volatile("st.shared::cluster.v4.f32 [%0], {%1,%2,%3,%4};"
                         :: "r"(dst +  96u), "f"(s6.x), "f"(s6.y), "f"(s6.z), "f"(s6.w) : "memory");
            asm volatile("st.shared::cluster.v4.f32 [%0], {%1,%2,%3,%4};"
                         :: "r"(dst + 112u), "f"(s7.x), "f"(s7.y), "f"(s7.z), "f"(s7.w) : "memory");
            asm volatile("mbarrier.arrive.release.cluster.shared::cluster.b64 _, [%0];"
                         :: "r"(rm[nb]) : "memory");
        }
    }

    // final h (step TB-1 wrote buf 0); wait for last arrivals
    if (l == 0) mbar_poll_cluster(mbb, ph[0]);
    __syncwarp();
    __syncthreads();
    if (rank == 0 && tid < H2) g_hT2[tid] = sh_h[0][tid];

    asm volatile("barrier.cluster.arrive.aligned;" ::: "memory");
    asm volatile("barrier.cluster.wait.aligned;" ::: "memory");
}

// ---------------- tail MLP ----------------
__global__ void mlp_kernel(const float* __restrict__ W1, const float* __restrict__ b1,
                           const float* __restrict__ W2, const float* __restrict__ b2,
                           float* __restrict__ out) {
    __shared__ float emb[H2];
    __shared__ float o1[128];
    int tid = threadIdx.x;  // 128
    {
        float h0 = g_hT2[tid];
        float h1 = g_hT2[tid + 128];
        emb[tid]       = h0 + h0 * h0;
        emb[tid + 128] = h1 + h1 * h1;
    }
    __syncthreads();
    float s = b1[tid];
    const float* wrow = W1 + (size_t)tid * H2;
#pragma unroll 8
    for (int k = 0; k < H2; k++) s = fmaf(emb[k], wrow[k], s);
    o1[tid] = s;
    __syncthreads();
    if (tid < 10) {
        float s2 = b2[tid];
        const float* w2r = W2 + (size_t)tid * 128;
#pragma unroll 8
        for (int k = 0; k < 128; k++) s2 = fmaf(o1[k], w2r[k], s2);
        out[tid] = s2;
    }
}

extern "C" void kernel_launch(void* const* d_in, const int* in_sizes, int n_in,
                              void* d_out, int out_size) {
    const float* x     = (const float*)d_in[0];
    const float* W_ih1 = (const float*)d_in[1];
    const float* W_hh1 = (const float*)d_in[2];
    const float* b_ih1 = (const float*)d_in[3];
    const float* b_hh1 = (const float*)d_in[4];
    const float* W_ih2 = (const float*)d_in[5];
    const float* W_hh2 = (const float*)d_in[6];
    const float* b_ih2 = (const float*)d_in[7];
    const float* b_hh2 = (const float*)d_in[8];
    const float* W1    = (const float*)d_in[9];
    const float* b1    = (const float*)d_in[10];
    const float* W2    = (const float*)d_in[11];
    const float* b2    = (const float*)d_in[12];
    float* out = (float*)d_out;

    const int LSTM1_SMEM = (32768 + 2 * 16 * WPAD + 1024) * 4;   // 168448 B
    cudaFuncSetAttribute(lstm1_persist, cudaFuncAttributeMaxDynamicSharedMemorySize,
                         LSTM1_SMEM);

    gemm64<0><<<dim3(G1N / 64, TB / 64), 256>>>(x, W_ih1, b_ih1, b_hh1);  // 0 (+g_bar reset)
    lstm1_persist<<<128, 512, LSTM1_SMEM>>>(W_hh1);                       // 1
    gemm64<1><<<dim3(G2N / 64, TB / 64), 256>>>(x, W_ih2, b_ih2, b_hh2);  // 2
    lstm2_kernel<<<8, 512>>>(W_hh2);                                      // 3 <- ncu slot
    mlp_kernel<<<1, 128>>>(W1, b1, W2, b2, out);                          // 4
}

// round 17
// speedup vs baseline: 1.8038x; 1.0184x over previous
#include <cuda_runtime.h>
#include <cuda_bf16.h>
#include <cstdint>

#define BATCH   64
#define TSTEPS  128
#define TB      8192
#define DIN     768
#define H1      512
#define G1N     2048
#define H2      256
#define G2N     1024

// ---------------- static device scratch (no allocations) ----------------
__device__ float g_G1[(size_t)TB * G1N];   // 64 MB
__device__ float g_G2[(size_t)TB * G2N];   // 32 MB
__device__ float g_hs1[(size_t)TB * H1];   // 16 MB
__device__ float g_hT[2][H1 * BATCH];      // h1 transposed [j][b], double-buffered
__device__ float g_hT2[H2];                // final LSTM2 hidden
__device__ unsigned g_bar;                 // lstm1 global barrier counter

__device__ __forceinline__ float sigf(float x) { return 1.0f / (1.0f + __expf(-x)); }
__device__ __forceinline__ float tanh_fast(float x) {
    float xc = fminf(fmaxf(x, -15.0f), 15.0f);
    float e = __expf(2.0f * xc);
    return __fdividef(e - 1.0f, e + 1.0f);
}

// ---------------- GEMM: C[M,N] = A[M,K] @ B[N,K]^T + bias1 + bias2 ----------------
template <int MODE>
__global__ void __launch_bounds__(256) gemm64(const float* __restrict__ A,
                                              const float* __restrict__ B,
                                              const float* __restrict__ bias1,
                                              const float* __restrict__ bias2) {
    constexpr int N = (MODE == 0) ? G1N : G2N;
    constexpr int K = (MODE == 0) ? DIN : H1;
    float* __restrict__ C = (MODE == 0) ? g_G1 : g_G2;
    const float* __restrict__ Ap = (MODE == 0) ? A : g_hs1;

    __shared__ float As[16][64];
    __shared__ float Bs[16][64];

    int tid = threadIdx.x;
    if (MODE == 0 && blockIdx.x == 0 && blockIdx.y == 0 && tid == 0) g_bar = 0u;

    int m0 = blockIdx.y * 64, n0 = blockIdx.x * 64;
    int tx = tid & 15, ty = tid >> 4;

    int la_m = tid & 63, la_k = (tid >> 6) * 4;
    int lb_n = tid >> 2, lb_k = (tid & 3) * 4;

    int r = m0 + la_m;
    size_t arow;
    if (MODE == 0) {
        int b = r & 63, t = r >> 6;
        arow = ((size_t)b * TSTEPS + t) * DIN;
    } else {
        arow = (size_t)r * K;
    }

    float acc[4][4];
#pragma unroll
    for (int i = 0; i < 4; i++)
#pragma unroll
        for (int j = 0; j < 4; j++) acc[i][j] = 0.0f;

    for (int kt = 0; kt < K; kt += 16) {
        float4 av = *(const float4*)(Ap + arow + kt + la_k);
        As[la_k + 0][la_m] = av.x;
        As[la_k + 1][la_m] = av.y;
        As[la_k + 2][la_m] = av.z;
        As[la_k + 3][la_m] = av.w;
        float4 bv = *(const float4*)(B + (size_t)(n0 + lb_n) * K + kt + lb_k);
        Bs[lb_k + 0][lb_n] = bv.x;
        Bs[lb_k + 1][lb_n] = bv.y;
        Bs[lb_k + 2][lb_n] = bv.z;
        Bs[lb_k + 3][lb_n] = bv.w;
        __syncthreads();
#pragma unroll
        for (int k = 0; k < 16; k++) {
            float4 a  = ((const float4*)As[k])[ty];
            float4 b4 = ((const float4*)Bs[k])[tx];
            acc[0][0] = fmaf(a.x, b4.x, acc[0][0]);
            acc[0][1] = fmaf(a.x, b4.y, acc[0][1]);
            acc[0][2] = fmaf(a.x, b4.z, acc[0][2]);
            acc[0][3] = fmaf(a.x, b4.w, acc[0][3]);
            acc[1][0] = fmaf(a.y, b4.x, acc[1][0]);
            acc[1][1] = fmaf(a.y, b4.y, acc[1][1]);
            acc[1][2] = fmaf(a.y, b4.z, acc[1][2]);
            acc[1][3] = fmaf(a.y, b4.w, acc[1][3]);
            acc[2][0] = fmaf(a.z, b4.x, acc[2][0]);
            acc[2][1] = fmaf(a.z, b4.y, acc[2][1]);
            acc[2][2] = fmaf(a.z, b4.z, acc[2][2]);
            acc[2][3] = fmaf(a.z, b4.w, acc[2][3]);
            acc[3][0] = fmaf(a.w, b4.x, acc[3][0]);
            acc[3][1] = fmaf(a.w, b4.y, acc[3][1]);
            acc[3][2] = fmaf(a.w, b4.z, acc[3][2]);
            acc[3][3] = fmaf(a.w, b4.w, acc[3][3]);
        }
        __syncthreads();
    }

    int coln = n0 + tx * 4;
    float bb0 = bias1[coln + 0] + bias2[coln + 0];
    float bb1 = bias1[coln + 1] + bias2[coln + 1];
    float bb2 = bias1[coln + 2] + bias2[coln + 2];
    float bb3 = bias1[coln + 3] + bias2[coln + 3];
#pragma unroll
    for (int i = 0; i < 4; i++) {
        int row = m0 + ty * 4 + i;
        float4 o;
        o.x = acc[i][0] + bb0;
        o.y = acc[i][1] + bb1;
        o.z = acc[i][2] + bb2;
        o.w = acc[i][3] + bb3;
        *(float4*)(C + (size_t)row * N + coln) = o;
    }
}

// ---------------- LSTM1: persistent, 128 blocks; load-based global barrier ----------------
#define WPAD 260      // padded weight row stride (floats)
__device__ __forceinline__ void gbar_sync(int tid, unsigned target) {
    __threadfence();              // release: drain h stores before arrive
    __syncthreads();
    if (tid == 0) {
        atomicAdd(&g_bar, 1u);
        unsigned v;
        do {
            asm volatile("ld.global.acquire.gpu.u32 %0, [%1];"
                         : "=r"(v) : "l"(&g_bar) : "memory");
            if (v >= target) break;
            __nanosleep(64);
        } while (true);
    }
    __syncthreads();
}

__global__ void __launch_bounds__(512) lstm1_persist(const float* __restrict__ Whh1) {
    extern __shared__ float dsm[];
    float* Hs  = dsm;                     // [2][16384]  128 KB
    float* Wsr = dsm + 32768;             // [2][16*WPAD] c-major, padded
    float* sg  = dsm + 32768 + 2 * 16 * WPAD;   // [16*64]

    int tid = threadIdx.x;
    int half = tid >> 8;       // k half: [half*256, half*256+256)
    int lt = tid & 255;
    int c  = lt & 15;          // local gate column 0..15
    int bg = lt >> 4;          // batch group 0..15
    int j0 = blockIdx.x * 4;
    int gg_ = c >> 2, u = c & 3;
    int gcol = gg_ * H1 + j0 + u;

    // zero g_hT[0]
    {
        int zid = blockIdx.x * 512 + tid;
        if (zid < H1 * BATCH) g_hT[0][zid] = 0.0f;
    }

    // resident weights, c-major padded: Wsr[half][wc*WPAD + k_local]
    {
        int wc = lt & 15, wk4 = lt >> 4;
        int wg = wc >> 2, wu = wc & 3;
        float* W = Wsr + half * 16 * WPAD;
#pragma unroll
        for (int kk = 0; kk < 4; kk++) {
            int ktl = kk * 64 + wk4 * 4;
            float4 wv = *(const float4*)(Whh1 + (size_t)(wg * H1 + j0 + wu) * H1 + half * 256 + ktl);
            *(float4*)(W + wc * WPAD + ktl) = wv;
        }
    }

    gbar_sync(tid, 128u);   // zeroing visible

    int u2 = tid >> 6, bb = tid & 63;
    float creg = 0.0f;

    for (int t = 0; t < TSTEPS; t++) {
        int rp = t & 1;
        {
            const float4* s4 = (const float4*)(g_hT[rp] + half * 16384);
            float4* d4 = (float4*)(Hs + half * 16384);
#pragma unroll
            for (int i = 0; i < 16; i++) d4[lt + i * 256] = __ldcg(&s4[lt + i * 256]);
        }
        __syncthreads();

        float a0 = 0.f, a1 = 0.f, a2 = 0.f, a3 = 0.f;
        const float* HH = Hs + half * 16384;
        const float* WR = Wsr + half * 16 * WPAD + c * WPAD;
#pragma unroll 8
        for (int k4 = 0; k4 < 64; k4++) {
            float4 w4 = *(const float4*)(WR + k4 * 4);
            int k = k4 * 4;
            float4 h0 = ((const float4*)(HH + (k + 0) * 64))[bg];
            a0 = fmaf(h0.x, w4.x, a0); a1 = fmaf(h0.y, w4.x, a1);
            a2 = fmaf(h0.z, w4.x, a2); a3 = fmaf(h0.w, w4.x, a3);
            float4 h1 = ((const float4*)(HH + (k + 1) * 64))[bg];
            a0 = fmaf(h1.x, w4.y, a0); a1 = fmaf(h1.y, w4.y, a1);
            a2 = fmaf(h1.z, w4.y, a2); a3 = fmaf(h1.w, w4.y, a3);
            float4 h2 = ((const float4*)(HH + (k + 2) * 64))[bg];
            a0 = fmaf(h2.x, w4.z, a0); a1 = fmaf(h2.y, w4.z, a1);
            a2 = fmaf(h2.z, w4.z, a2); a3 = fmaf(h2.w, w4.z, a3);
            float4 h3 = ((const float4*)(HH + (k + 3) * 64))[bg];
            a0 = fmaf(h3.x, w4.w, a0); a1 = fmaf(h3.y, w4.w, a1);
            a2 = fmaf(h3.z, w4.w, a2); a3 = fmaf(h3.w, w4.w, a3);
        }

        int b0 = bg * 4;
        if (half == 0) {
            size_t gbase = ((size_t)(t * BATCH + b0)) * G1N + gcol;
            sg[c * 64 + b0 + 0] = a0 + g_G1[gbase];
            sg[c * 64 + b0 + 1] = a1 + g_G1[gbase + G1N];
            sg[c * 64 + b0 + 2] = a2 + g_G1[gbase + 2 * (size_t)G1N];
            sg[c * 64 + b0 + 3] = a3 + g_G1[gbase + 3 * (size_t)G1N];
        }
        __syncthreads();
        if (half == 1) {
            sg[c * 64 + b0 + 0] += a0;
            sg[c * 64 + b0 + 1] += a1;
            sg[c * 64 + b0 + 2] += a2;
            sg[c * 64 + b0 + 3] += a3;
        }
        __syncthreads();

        if (tid < 256) {
            float gi = sigf(sg[(0 * 4 + u2) * 64 + bb]);
            float gf = sigf(sg[(1 * 4 + u2) * 64 + bb]);
            float gc = tanh_fast(sg[(2 * 4 + u2) * 64 + bb]);
            float go = sigf(sg[(3 * 4 + u2) * 64 + bb]);
            int jj = j0 + u2;
            creg = fmaf(gf, creg, gi * gc);
            float h = go * tanh_fast(creg);
            g_hT[rp ^ 1][jj * BATCH + bb] = h;
            g_hs1[((size_t)(t * BATCH + bb)) * H1 + jj] = h;
        }

        if (t < TSTEPS - 1) gbar_sync(tid, 128u * (unsigned)(t + 2));
    }
}

// ---------------- LSTM2: cluster of 8, seqlock flag sync (no mbarriers) ----------------
// Writers ship h slice with plain remote stores, then st.release a monotonic step
// counter into the peer's sh_flag[buf][src]. Receivers spin on cheap local
// ld.acquire (every lane acquires -> all lanes' h loads ordered).
__global__ void __cluster_dims__(8, 1, 1) __launch_bounds__(512, 1)
lstm2_kernel(const float* __restrict__ Whh2) {
    __shared__ __align__(16) float sh_h[2][H2];      // replicated h, double-buffered
    __shared__ __align__(16) float sh_stage[32];     // this CTA's 32 new h values
    __shared__ __align__(16) unsigned sh_flag[2][8]; // [buf][src]: last step posted

    int tid = threadIdx.x;
    int w = tid >> 5, l = tid & 31;
    uint32_t rank;
    asm("mov.u32 %0, %%cluster_ctarank;" : "=r"(rank));

    // warp-local mapping: warp w owns units {2w, 2w+1}
    int j  = 2 * w + (l & 1);     // unit within CTA slice
    int kq = (l >> 1) & 3;        // k quarter
    int g  = l >> 3;              // gate 0=i 1=f 2=g 3=o
    int gr = g * H2 + (int)rank * 32 + j;
    bool isU = ((l & 6) == 0);    // kq==0 lanes

    // weights: 64 floats of row gr, quarter kq, packed f32x2
    unsigned long long w2[32];
    {
        const ulonglong2* wp = (const ulonglong2*)(Whh2 + (size_t)gr * H2 + kq * 64);
#pragma unroll
        for (int i = 0; i < 16; i++) {
            ulonglong2 v = wp[i];
            w2[2 * i] = v.x; w2[2 * i + 1] = v.y;
        }
    }

    if (tid < H2) sh_h[0][tid] = 0.0f;
    if (tid < 16) sh_flag[tid >> 3][tid & 7] = 0u;
    __syncthreads();
    asm volatile("barrier.cluster.arrive.aligned;" ::: "memory");
    asm volatile("barrier.cluster.wait.aligned;" ::: "memory");

    // writer warp (warp 0) lanes 0-7: lane d owns peer d
    uint32_t rh[2], rf[2];
    uint32_t hb = (uint32_t)__cvta_generic_to_shared(&sh_h[0][0]);
    uint32_t fb = (uint32_t)__cvta_generic_to_shared(&sh_flag[0][0]);
    if (w == 0 && l < 8) {
        int d = l;
        uint32_t l0 = hb + (uint32_t)((int)rank * 32) * 4u;        // buf0 slice base
        uint32_t l1 = l0 + H2 * 4u;                                // buf1 slice base
        uint32_t f0 = fb + (uint32_t)(0 * 8 + (int)rank) * 4u;     // sh_flag[0][rank]
        uint32_t f1 = fb + (uint32_t)(1 * 8 + (int)rank) * 4u;     // sh_flag[1][rank]
        asm("mapa.shared::cluster.u32 %0, %1, %2;" : "=r"(rh[0]) : "r"(l0), "r"(d));
        asm("mapa.shared::cluster.u32 %0, %1, %2;" : "=r"(rh[1]) : "r"(l1), "r"(d));
        asm("mapa.shared::cluster.u32 %0, %1, %2;" : "=r"(rf[0]) : "r"(f0), "r"(d));
        asm("mapa.shared::cluster.u32 %0, %1, %2;" : "=r"(rf[1]) : "r"(f1), "r"(d));
    }
    uint32_t stg = (uint32_t)__cvta_generic_to_shared(&sh_stage[0]);

    float c = 0.0f;
    float u_next = isU ? __ldg(&g_G2[gr]) : 0.0f;

    for (int r = 0; r < TB; r++) {
        int buf = r & 1;
        // poll: every lane acquires flag[buf][l&7]; r=0 passes trivially (v>=0)
        {
            uint32_t fa = fb + (uint32_t)(buf * 8 + (l & 7)) * 4u;
            unsigned v;
            do {
                asm volatile("ld.acquire.cluster.shared::cta.u32 %0, [%1];"
                             : "=r"(v) : "r"(fa) : "memory");
            } while (!__all_sync(0xffffffffu, v >= (unsigned)r));
        }

        float u = u_next;
        if (isU && r + 1 < TB) u_next = __ldg(&g_G2[(size_t)(r + 1) * G2N + gr]);

        const ulonglong2* hp = (const ulonglong2*)(&sh_h[buf][kq * 64]);
        unsigned long long acc01 = 0ull, acc23 = 0ull;
#pragma unroll
        for (int i = 0; i < 16; i++) {
            ulonglong2 hv = hp[i];
            asm("fma.rn.f32x2 %0, %1, %2, %3;" : "=l"(acc01) : "l"(w2[2 * i]), "l"(hv.x), "l"(acc01));
            asm("fma.rn.f32x2 %0, %1, %2, %3;" : "=l"(acc23) : "l"(w2[2 * i + 1]), "l"(hv.y), "l"(acc23));
        }
        float acc = (__uint_as_float((unsigned)acc01) + __uint_as_float((unsigned)(acc01 >> 32)))
                  + (__uint_as_float((unsigned)acc23) + __uint_as_float((unsigned)(acc23 >> 32)));
        acc += __shfl_xor_sync(0xffffffffu, acc, 2);   // reduce kq (lane bits 1-2)
        acc += __shfl_xor_sync(0xffffffffu, acc, 4);

        float act = 0.0f;
        if (isU) {
            float pre = acc + u;
            act = (g == 2) ? tanh_fast(pre) : sigf(pre);
        }
        int jb = l & 1;
        float gi = __shfl_sync(0xffffffffu, act, jb);
        float gf = __shfl_sync(0xffffffffu, act, 8 | jb);
        float gg = __shfl_sync(0xffffffffu, act, 16 | jb);
        float go = __shfl_sync(0xffffffffu, act, 24 | jb);

        c = fmaf(gf, c, gi * gg);          // redundant across lanes sharing unit j
        float h = go * tanh_fast(c);

        if (l < 2) sh_stage[2 * w + l] = h;   // lane0 -> unit 2w, lane1 -> unit 2w+1
        __syncthreads();   // stage complete; also closes WAR on sh_h[buf] before peers overwrite

        int nb = buf ^ 1;
        unsigned vpost = (unsigned)(r + 1);
        if (w == 0 && l < 8) {
            float4 s0 = *(const float4*)(&sh_stage[0]);
            float4 s1 = *(const float4*)(&sh_stage[4]);
            float4 s2 = *(const float4*)(&sh_stage[8]);
            float4 s3 = *(const float4*)(&sh_stage[12]);
            float4 s4 = *(const float4*)(&sh_stage[16]);
            float4 s5 = *(const float4*)(&sh_stage[20]);
            float4 s6 = *(const float4*)(&sh_stage[24]);
            float4 s7 = *(const float4*)(&sh_stage[28]);
            uint32_t dst = (nb == 0) ? rh[0] : rh[1];
            asm volatile("st.shared::cluster.v4.f32 [%0], {%1,%2,%3,%4};"
                         :: "r"(dst +   0u), "f"(s0.x), "f"(s0.y), "f"(s0.z), "f"(s0.w) : "memory");
            asm volatile("st.shared::cluster.v4.f32 [%0], {%1,%2,%3,%4};"
                         :: "r"(dst +  16u), "f"(s1.x), "f"(s1.y), "f"(s1.z), "f"(s1.w) : "memory");
            asm volatile("st.shared::cluster.v4.f32 [%0], {%1,%2,%3,%4};"
                         :: "r"(dst +  32u), "f"(s2.x), "f"(s2.y), "f"(s2.z), "f"(s2.w) : "memory");
            asm volatile("st.shared::cluster.v4.f32 [%0], {%1,%2,%3,%4};"
                         :: "r"(dst +  48u), "f"(s3.x), "f"(s3.y), "f"(s3.z), "f"(s3.w) : "memory");
            asm volatile("st.shared::cluster.v4.f32 [%0], {%1,%2,%3,%4};"
                         :: "r"(dst +  64u), "f"(s4.x), "f"(s4.y), "f"(s4.z), "f"(s4.w) : "memory");
            asm volatile("st.shared::cluster.v4.f32 [%0], {%1,%2,%3,%4};"
                         :: "r"(dst +  80u), "f"(s5.x), "f"(s5.y), "f"(s5.z), "f"(s5.w) : "memory");
            asm volatile("st.shared::cluster.v4.f32 [%0], {%1,%2,%3,%4};"
                         :: "r"(dst +  96u), "f"(s6.x), "f"(s6.y), "f"(s6.z), "f"(s6.w) : "memory");
            asm volatile("st.shared::cluster.v4.f32 [%0], {%1,%2,%3,%4};"
                         :: "r"(dst + 112u), "f"(s7.x), "f"(s7.y), "f"(s7.z), "f"(s7.w) : "memory");
            uint32_t fdst = (nb == 0) ? rf[0] : rf[1];
            asm volatile("st.release.cluster.shared::cluster.u32 [%0], %1;"
                         :: "r"(fdst), "r"(vpost) : "memory");
        }
    }

    // final h (step TB posted into buf 0 with value TB)
    {
        uint32_t fa = fb + (uint32_t)(0 * 8 + (l & 7)) * 4u;
        unsigned v;
        do {
            asm volatile("ld.acquire.cluster.shared::cta.u32 %0, [%1];"
                         : "=r"(v) : "r"(fa) : "memory");
        } while (!__all_sync(0xffffffffu, v >= (unsigned)TB));
    }
    __syncthreads();
    if (rank == 0 && tid < H2) g_hT2[tid] = sh_h[0][tid];

    asm volatile("barrier.cluster.arrive.aligned;" ::: "memory");
    asm volatile("barrier.cluster.wait.aligned;" ::: "memory");
}

// ---------------- tail MLP ----------------
__global__ void mlp_kernel(const float* __restrict__ W1, const float* __restrict__ b1,
                           const float* __restrict__ W2, const float* __restrict__ b2,
                           float* __restrict__ out) {
    __shared__ float emb[H2];
    __shared__ float o1[128];
    int tid = threadIdx.x;  // 128
    {
        float h0 = g_hT2[tid];
        float h1 = g_hT2[tid + 128];
        emb[tid]       = h0 + h0 * h0;
        emb[tid + 128] = h1 + h1 * h1;
    }
    __syncthreads();
    float s = b1[tid];
    const float* wrow = W1 + (size_t)tid * H2;
#pragma unroll 8
    for (int k = 0; k < H2; k++) s = fmaf(emb[k], wrow[k], s);
    o1[tid] = s;
    __syncthreads();
    if (tid < 10) {
        float s2 = b2[tid];
        const float* w2r = W2 + (size_t)tid * 128;
#pragma unroll 8
        for (int k = 0; k < 128; k++) s2 = fmaf(o1[k], w2r[k], s2);
        out[tid] = s2;
    }
}

extern "C" void kernel_launch(void* const* d_in, const int* in_sizes, int n_in,
                              void* d_out, int out_size) {
    const float* x     = (const float*)d_in[0];
    const float* W_ih1 = (const float*)d_in[1];
    const float* W_hh1 = (const float*)d_in[2];
    const float* b_ih1 = (const float*)d_in[3];
    const float* b_hh1 = (const float*)d_in[4];
    const float* W_ih2 = (const float*)d_in[5];
    const float* W_hh2 = (const float*)d_in[6];
    const float* b_ih2 = (const float*)d_in[7];
    const float* b_hh2 = (const float*)d_in[8];
    const float* W1    = (const float*)d_in[9];
    const float* b1    = (const float*)d_in[10];
    const float* W2    = (const float*)d_in[11];
    const float* b2    = (const float*)d_in[12];
    float* out = (float*)d_out;

    const int LSTM1_SMEM = (32768 + 2 * 16 * WPAD + 1024) * 4;   // 168448 B
    cudaFuncSetAttribute(lstm1_persist, cudaFuncAttributeMaxDynamicSharedMemorySize,
                         LSTM1_SMEM);

    gemm64<0><<<dim3(G1N / 64, TB / 64), 256>>>(x, W_ih1, b_ih1, b_hh1);  // 0 (+g_bar reset)
    lstm1_persist<<<128, 512, LSTM1_SMEM>>>(W_hh1);                       // 1
    gemm64<1><<<dim3(G2N / 64, TB / 64), 256>>>(x, W_ih2, b_ih2, b_hh2);  // 2
    lstm2_kernel<<<8, 512>>>(W_hh2);                                      // 3 <- ncu slot
    mlp_kernel<<<1, 128>>>(W1, b1, W2, b2, out);                          // 4
}